// round 11
// baseline (speedup 1.0000x reference)
#include <cuda_runtime.h>
#include <cuda_bf16.h>
#include <cstdint>

#define BB 256
#define TT 20
#define HH 512
#define WVV 301
#define FF 196
#define CC 512
#define VV 9871
#define XK 813
#define NAG 708

#define KSEC 832          // padded K section (>=813, mult of 32)
#define LKP 2496          // 3 * KSEC
#define SPL 6             // split-K slices
#define KCH 416           // K per slice = LKP / SPL
#define NITS 13           // 416 / 32

#define KP 1536           // vocab split K = 3*512
#define NPAD 9984
#define MROWS (TT * BB)   // 5120

// ---------------- device globals ------------------------------------------------
__device__ __nv_bfloat16 g_Aattn[(size_t)TT * BB * LKP];  // [x|h] hi/hi/lo triple
__device__ __nv_bfloat16 g_Acomb[(size_t)TT * BB * LKP];  // [x|ctx]
__device__ __nv_bfloat16 g_Aih[(size_t)BB * LKP];         // [inp|h]
__device__ __nv_bfloat16 g_Wag2[(size_t)768 * LKP];       // [Whi|Wlo|Whi]
__device__ __nv_bfloat16 g_Wcomb2[(size_t)320 * LKP];
__device__ __nv_bfloat16 g_Wl2[(size_t)2048 * LKP];
__device__ float g_ag_s[SPL * BB * 768];     // attn+gate logit slices
__device__ float g_comb_s[SPL * BB * 320];   // comb raw slices (padded N=320)
__device__ float g_gate_s[SPL * BB * 2048];  // lstm gate slices
__device__ float g_cst[BB * HH];             // cell state
__device__ float g_bl[2048];                 // bih + bhh
__device__ __nv_bfloat16 g_ap[(size_t)MROWS * KP];  // vocab A'' [hi|hi|lo]
__device__ __nv_bfloat16 g_wp[(size_t)NPAD * KP];   // vocab W'' [hi|lo|hi]

// ---------------- common helpers ------------------------------------------------
__device__ __forceinline__ uint32_t smem_u32(const void* p) {
    uint32_t a;
    asm("{ .reg .u64 t; cvta.to.shared.u64 t, %1; cvt.u32.u64 %0, t; }" : "=r"(a) : "l"(p));
    return a;
}
__device__ __forceinline__ void cp16(uint32_t saddr, const void* gptr) {
    asm volatile("cp.async.cg.shared.global [%0], [%1], 16;" :: "r"(saddr), "l"(gptr));
}
__device__ __forceinline__ void cp_commit() { asm volatile("cp.async.commit_group;"); }
template <int N>
__device__ __forceinline__ void cp_wait() { asm volatile("cp.async.wait_group %0;" :: "n"(N)); }
__device__ __forceinline__ void ldm_x4(uint32_t* r, uint32_t addr) {
    asm volatile("ldmatrix.sync.aligned.m8n8.x4.shared.b16 {%0,%1,%2,%3}, [%4];"
                 : "=r"(r[0]), "=r"(r[1]), "=r"(r[2]), "=r"(r[3]) : "r"(addr));
}
__device__ __forceinline__ void mma_bf16(float* c, const uint32_t* a, uint32_t b0, uint32_t b1) {
    asm volatile(
        "mma.sync.aligned.m16n8k16.row.col.f32.bf16.bf16.f32 "
        "{%0,%1,%2,%3}, {%4,%5,%6,%7}, {%8,%9}, {%0,%1,%2,%3};"
        : "+f"(c[0]), "+f"(c[1]), "+f"(c[2]), "+f"(c[3])
        : "r"(a[0]), "r"(a[1]), "r"(a[2]), "r"(a[3]), "r"(b0), "r"(b1));
}
// 64B-row swizzle for BK=32 tiles
__device__ __forceinline__ uint32_t swz(int row, int c) {
    return (uint32_t)(row * 64 + ((c ^ ((row >> 1) & 3)) * 16));
}
__device__ __forceinline__ void split_bf16(float v, __nv_bfloat16& hi, __nv_bfloat16& lo) {
    hi = __float2bfloat16(v);
    lo = __float2bfloat16(v - __bfloat162float(hi));
}

// 64x64 tile bf16 GEMM over NIT k-chunks of 32 starting at koff.
// 6-stage cp.async pipeline, 5 groups in flight. blockDim = 256. (R7 proven)
template <int NIT>
__device__ __forceinline__ void tile_mma(const __nv_bfloat16* __restrict__ Ag,
                                         const __nv_bfloat16* __restrict__ Bg,
                                         int bm, int bn, int koff, char* spipe,
                                         float acc[4][4]) {
    uint32_t smb = smem_u32(spipe);
    int tid = threadIdx.x;
    int wid = tid >> 5, lane = tid & 31;
    int wm = wid & 3, wn = wid >> 2;
    int a_r = lane & 15, a_c = lane >> 4;
    int b_r = (lane & 7) | (((lane >> 4) & 1) << 3);
    int b_c = (lane >> 3) & 1;
    int lrow = tid >> 2, lc = tid & 3;
#pragma unroll
    for (int q = 0; q < 4; q++)
#pragma unroll
        for (int j = 0; j < 4; j++) acc[q][j] = 0.f;

    const __nv_bfloat16* Abase = Ag + (size_t)(bm + lrow) * LKP + koff + lc * 8;
    const __nv_bfloat16* Bbase = Bg + (size_t)(bn + lrow) * LKP + koff + lc * 8;

#pragma unroll
    for (int st = 0; st < 5; st++) {
        if (st < NIT) {
            uint32_t ab = smb + st * 8192;
            cp16(ab + swz(lrow, lc), Abase + st * 32);
            cp16(ab + 4096 + swz(lrow, lc), Bbase + st * 32);
        }
        cp_commit();
    }
    for (int kt = 0; kt < NIT; kt++) {
        cp_wait<4>();
        __syncthreads();
        int nx = kt + 5;
        if (nx < NIT) {
            uint32_t ab = smb + (nx % 6) * 8192;
            cp16(ab + swz(lrow, lc), Abase + (size_t)nx * 32);
            cp16(ab + 4096 + swz(lrow, lc), Bbase + (size_t)nx * 32);
        }
        cp_commit();
        uint32_t ab = smb + (kt % 6) * 8192;
        uint32_t bb = ab + 4096;
#pragma unroll
        for (int s = 0; s < 2; s++) {
            uint32_t af[4];
            ldm_x4(af, ab + swz(wm * 16 + a_r, s * 2 + a_c));
#pragma unroll
            for (int jj = 0; jj < 2; jj++) {
                uint32_t bf[4];
                ldm_x4(bf, bb + swz(wn * 32 + jj * 16 + b_r, s * 2 + b_c));
                mma_bf16(acc[2 * jj], af, bf[0], bf[1]);
                mma_bf16(acc[2 * jj + 1], af, bf[2], bf[3]);
            }
        }
        __syncthreads();
    }
}

// ---------------- setup kernels (3 launches before loop) ------------------------
__global__ void zero_all_kernel() {
    size_t stride = (size_t)gridDim.x * blockDim.x;
    size_t id = (size_t)blockIdx.x * blockDim.x + threadIdx.x;
    uint4 z = make_uint4(0, 0, 0, 0);
    uint4* pa = (uint4*)g_Aattn;
    size_t nA = sizeof(g_Aattn) / 16;
    for (size_t i = id; i < nA; i += stride) pa[i] = z;
    uint4* pc = (uint4*)g_Acomb;
    for (size_t i = id; i < nA; i += stride) pc[i] = z;
    uint4* pi = (uint4*)g_Aih;
    size_t nI = sizeof(g_Aih) / 16;
    for (size_t i = id; i < nI; i += stride) pi[i] = z;
    uint4* ps = (uint4*)g_cst;
    size_t nS = sizeof(g_cst) / 16;
    for (size_t i = id; i < nS; i += stride) ps[i] = z;
}

__global__ void setup_x2_kernel(const float* __restrict__ wv) {
    int idx = blockIdx.x * blockDim.x + threadIdx.x;
    const int total = TT * BB * WVV;
    if (idx >= total) return;
    int t = idx / (BB * WVV);
    int r = idx % (BB * WVV);
    int b = r / WVV, w = r % WVV;
    float v = (t == 0) ? 0.f : wv[(size_t)b * TT * WVV + (size_t)(t - 1) * WVV + w];
    __nv_bfloat16 hi, lo;
    split_bf16(v, hi, lo);
    size_t base = ((size_t)t * BB + b) * LKP;
    g_Aattn[base + w] = hi;
    g_Aattn[base + KSEC + w] = hi;
    g_Aattn[base + 2 * KSEC + w] = lo;
    g_Acomb[base + w] = hi;
    g_Acomb[base + KSEC + w] = hi;
    g_Acomb[base + 2 * KSEC + w] = lo;
}

// merged weight prep: wag2 | wcomb2 | wl2 | wp | bl
#define NW0 (768 * KSEC)
#define NW1 (320 * KSEC)
#define NW2 (2048 * KSEC)
#define NW3 (NPAD * HH)
__global__ void setup_weights_kernel(const float* __restrict__ attn_W,
                                     const float* __restrict__ gate_W,
                                     const float* __restrict__ comb_W,
                                     const float* __restrict__ Wih,
                                     const float* __restrict__ Whh,
                                     const float* __restrict__ bih,
                                     const float* __restrict__ bhh,
                                     const float* __restrict__ vw) {
    long idx = (long)blockIdx.x * blockDim.x + threadIdx.x;
    if (idx < 2048) g_bl[idx] = bih[idx] + bhh[idx];
    if (idx < NW0) {
        int n = idx / KSEC, k = idx % KSEC;
        float v = 0.f;
        if (k < XK) {
            if (n < FF) v = attn_W[(size_t)n * XK + k];
            else if (n < NAG && k >= WVV) v = gate_W[(size_t)(n - FF) * HH + (k - WVV)];
        }
        __nv_bfloat16 hi, lo;
        split_bf16(v, hi, lo);
        size_t base = (size_t)n * LKP;
        g_Wag2[base + k] = hi;
        g_Wag2[base + KSEC + k] = lo;
        g_Wag2[base + 2 * KSEC + k] = hi;
        return;
    }
    idx -= NW0;
    if (idx < NW1) {
        int n = idx / KSEC, k = idx % KSEC;
        float v = (n < WVV && k < XK) ? comb_W[(size_t)n * XK + k] : 0.f;
        __nv_bfloat16 hi, lo;
        split_bf16(v, hi, lo);
        size_t base = (size_t)n * LKP;
        g_Wcomb2[base + k] = hi;
        g_Wcomb2[base + KSEC + k] = lo;
        g_Wcomb2[base + 2 * KSEC + k] = hi;
        return;
    }
    idx -= NW1;
    if (idx < NW2) {
        int n = idx / KSEC, k = idx % KSEC;
        float v = 0.f;
        if (k < XK) v = (k < WVV) ? Wih[(size_t)n * WVV + k] : Whh[(size_t)n * HH + (k - WVV)];
        __nv_bfloat16 hi, lo;
        split_bf16(v, hi, lo);
        size_t base = (size_t)n * LKP;
        g_Wl2[base + k] = hi;
        g_Wl2[base + KSEC + k] = lo;
        g_Wl2[base + 2 * KSEC + k] = hi;
        return;
    }
    idx -= NW2;
    if (idx < NW3) {
        int n = idx / HH, k = idx % HH;
        float v = (n < VV) ? vw[(size_t)n * HH + k] : 0.f;
        __nv_bfloat16 hi, lo;
        split_bf16(v, hi, lo);
        size_t base = (size_t)n * KP;
        g_wp[base + k] = hi;
        g_wp[base + HH + k] = lo;
        g_wp[base + 2 * HH + k] = hi;
    }
}

// ---------------- loop kernels ---------------------------------------------------
// P1: attn+gate logits, split-K x6. grid = 288
__global__ void __launch_bounds__(256) k_p1(const __nv_bfloat16* __restrict__ A) {
    __shared__ __align__(16) char s_pipe[6 * 8192];
    float acc[4][4];
    int job = blockIdx.x;
    int z = job % SPL, tile = job / SPL;
    int bm = (tile / 12) * 64, bn = (tile % 12) * 64;
    tile_mma<NITS>(A, g_Wag2, bm, bn, z * KCH, s_pipe, acc);
    int tid = threadIdx.x, wid = tid >> 5, lane = tid & 31;
    float* dst = g_ag_s + (size_t)z * BB * 768;
    int r0 = bm + (wid & 3) * 16 + (lane >> 2);
    int c0 = bn + (wid >> 2) * 32 + 2 * (lane & 3);
#pragma unroll
    for (int q = 0; q < 4; q++)
#pragma unroll
        for (int h = 0; h < 2; h++) {
            dst[(r0 + 8 * h) * 768 + c0 + q * 8] = acc[q][2 * h];
            dst[(r0 + 8 * h) * 768 + c0 + q * 8 + 1] = acc[q][2 * h + 1];
        }
}

// P2: softmax + gated ctx (sums 6 slices). grid = BB
__global__ void __launch_bounds__(256) 
k_p2(const float* __restrict__ enc, const float* __restrict__ attn_b,
     const float* __restrict__ gate_b, __nv_bfloat16* __restrict__ Acomb_t) {
    __shared__ float s_red[256];
    __shared__ __align__(16) float s_aw[196];
    int b = blockIdx.x;
    int tid = threadIdx.x;
    int wid = tid >> 5, lane = tid & 31;
    const float* pb = g_ag_s + (size_t)b * 768;
    float v = -3.0e38f;
    if (tid < FF) {
        v = attn_b[tid];
#pragma unroll
        for (int z = 0; z < SPL; z++) v += pb[(size_t)z * BB * 768 + tid];
    }
    s_red[tid] = v;
    __syncthreads();
    for (int s = 128; s > 0; s >>= 1) {
        if (tid < s) s_red[tid] = fmaxf(s_red[tid], s_red[tid + s]);
        __syncthreads();
    }
    float mx = s_red[0];
    __syncthreads();
    float e = (tid < FF) ? expf(v - mx) : 0.f;
    s_red[tid] = e;
    __syncthreads();
    for (int s = 128; s > 0; s >>= 1) {
        if (tid < s) s_red[tid] += s_red[tid + s];
        __syncthreads();
    }
    float inv = 1.f / s_red[0];
    __syncthreads();
    if (tid < FF) s_aw[tid] = e * inv;
    __syncthreads();
    const float4* sa4 = (const float4*)s_aw;
    const float4* encb = (const float4*)(enc + (size_t)b * CC * FF);
    size_t cbase = (size_t)b * LKP;
    for (int grp = 0; grp < 8; grp++) {
#pragma unroll
        for (int ci = 0; ci < 8; ci++) {
            int c = wid * 64 + grp * 8 + ci;
            const float4* row = encb + (size_t)c * 49;
            float4 a0 = sa4[lane];
            float4 v0 = row[lane];
            float sum = v0.x * a0.x + v0.y * a0.y + v0.z * a0.z + v0.w * a0.w;
            if (lane < 17) {
                float4 a1 = sa4[lane + 32];
                float4 v1 = row[lane + 32];
                sum += v1.x * a1.x + v1.y * a1.y + v1.z * a1.z + v1.w * a1.w;
            }
#pragma unroll
            for (int o = 16; o > 0; o >>= 1) sum += __shfl_xor_sync(0xffffffffu, sum, o);
            if (lane == 0) {
                float gz = gate_b[c];
#pragma unroll
                for (int z = 0; z < SPL; z++) gz += pb[(size_t)z * BB * 768 + FF + c];
                float gamma = 1.f / (1.f + expf(-gz));
                float val = gamma * sum;
                __nv_bfloat16 hi, lo;
                split_bf16(val, hi, lo);
                Acomb_t[cbase + WVV + c] = hi;
                Acomb_t[cbase + KSEC + WVV + c] = hi;
                Acomb_t[cbase + 2 * KSEC + WVV + c] = lo;
            }
        }
    }
}

// P3: comb gemm, split-K x6, slice output. grid = 120
__global__ void __launch_bounds__(256)
k_p3(const __nv_bfloat16* __restrict__ A) {
    __shared__ __align__(16) char s_pipe[6 * 8192];
    float acc[4][4];
    int job = blockIdx.x;
    int z = job % SPL, tile = job / SPL;
    int bm = (tile / 5) * 64, bn = (tile % 5) * 64;
    tile_mma<NITS>(A, g_Wcomb2, bm, bn, z * KCH, s_pipe, acc);
    int tid = threadIdx.x, wid = tid >> 5, lane = tid & 31;
    float* dst = g_comb_s + (size_t)z * BB * 320;
    int r0 = bm + (wid & 3) * 16 + (lane >> 2);
    int c0 = bn + (wid >> 2) * 32 + 2 * (lane & 3);
#pragma unroll
    for (int q = 0; q < 4; q++)
#pragma unroll
        for (int h = 0; h < 2; h++) {
            dst[(r0 + 8 * h) * 320 + c0 + q * 8] = acc[q][2 * h];
            dst[(r0 + 8 * h) * 320 + c0 + q * 8 + 1] = acc[q][2 * h + 1];
        }
}

// P3b: reduce 6 comb slices + bias + relu -> g_Aih triple. grid = 302
__global__ void __launch_bounds__(256)
k_p3b(const float* __restrict__ comb_b) {
    int idx = blockIdx.x * 256 + threadIdx.x;
    if (idx >= BB * WVV) return;
    int b = idx / WVV, w = idx % WVV;
    float s = comb_b[w];
#pragma unroll
    for (int z = 0; z < SPL; z++) s += g_comb_s[((size_t)z * BB + b) * 320 + w];
    s = fmaxf(s, 0.f);
    __nv_bfloat16 hi, lo;
    split_bf16(s, hi, lo);
    size_t ib = (size_t)b * LKP + w;
    g_Aih[ib] = hi;
    g_Aih[ib + KSEC] = hi;
    g_Aih[ib + 2 * KSEC] = lo;
}

// P4: lstm gates gemm, split-K x6, slice output. grid = 768
__global__ void __launch_bounds__(256) k_p4() {
    __shared__ __align__(16) char s_pipe[6 * 8192];
    float acc[4][4];
    int job = blockIdx.x;
    int z = job % SPL, tile = job / SPL;
    int bm = (tile / 32) * 64, bn = (tile % 32) * 64;
    tile_mma<NITS>(g_Aih, g_Wl2, bm, bn, z * KCH, s_pipe, acc);
    int tid = threadIdx.x, wid = tid >> 5, lane = tid & 31;
    float* dst = g_gate_s + (size_t)z * BB * 2048;
    int r0 = bm + (wid & 3) * 16 + (lane >> 2);
    int c0 = bn + (wid >> 2) * 32 + 2 * (lane & 3);
#pragma unroll
    for (int q = 0; q < 4; q++)
#pragma unroll
        for (int h = 0; h < 2; h++) {
            dst[(r0 + 8 * h) * 2048 + c0 + q * 8] = acc[q][2 * h];
            dst[(r0 + 8 * h) * 2048 + c0 + q * 8 + 1] = acc[q][2 * h + 1];
        }
}

// P5: LSTM cell elementwise, sums 6 gate slices. grid = 512
__global__ void __launch_bounds__(256)
k_p5(int t, __nv_bfloat16* __restrict__ Aattn_next) {
    int idx = blockIdx.x * 256 + threadIdx.x;
    int b = idx >> 9, j = idx & 511;
    size_t gb = (size_t)b * 2048;
    float i_ = g_bl[j], f_ = g_bl[512 + j], g_ = g_bl[1024 + j], o_ = g_bl[1536 + j];
#pragma unroll
    for (int z = 0; z < SPL; z++) {
        const float* gr = g_gate_s + (size_t)z * BB * 2048 + gb;
        i_ += gr[j];
        f_ += gr[512 + j];
        g_ += gr[1024 + j];
        o_ += gr[1536 + j];
    }
    float si = 1.f / (1.f + expf(-i_));
    float sf = 1.f / (1.f + expf(-f_));
    float so = 1.f / (1.f + expf(-o_));
    float cn = sf * g_cst[idx] + si * tanhf(g_);
    float hn = so * tanhf(cn);
    g_cst[idx] = cn;
    __nv_bfloat16 hi, lo;
    split_bf16(hn, hi, lo);
    size_t ib = (size_t)b * LKP + WVV + j;
    g_Aih[ib] = hi;
    g_Aih[ib + KSEC] = hi;
    g_Aih[ib + 2 * KSEC] = lo;
    if (Aattn_next) {
        size_t ab = (size_t)b * LKP + WVV + j;
        Aattn_next[ab] = hi;
        Aattn_next[ab + KSEC] = hi;
        Aattn_next[ab + 2 * KSEC] = lo;
    }
    size_t vb = ((size_t)t * BB + b) * KP;
    g_ap[vb + j] = hi;
    g_ap[vb + HH + j] = hi;
    g_ap[vb + 2 * HH + j] = lo;
}

// ===================== vocab GEMM (batched rows, side stream) ===================
#define VBM 128
#define VBN 256
#define NKT (KP / 32)      // 48
#define STAGE_BYTES 24576
#define ASZ 8192
#define NSTAGE 3
#define VSMEM (NSTAGE * STAGE_BYTES)

__device__ __forceinline__ void issue_tile(const __nv_bfloat16* __restrict__ Ag,
                                           const __nv_bfloat16* __restrict__ Bg,
                                           uint32_t smb, int stage, int bm, int bn, int kt) {
    int tid = threadIdx.x;
    uint32_t abase = smb + stage * STAGE_BYTES;
    uint32_t bbase = abase + ASZ;
#pragma unroll
    for (int l = 0; l < 2; l++) {
        int idx = tid + 256 * l;
        int row = idx >> 2, c = idx & 3;
        cp16(abase + swz(row, c), Ag + (size_t)(bm + row) * KP + kt * 32 + c * 8);
    }
#pragma unroll
    for (int l = 0; l < 4; l++) {
        int idx = tid + 256 * l;
        int row = idx >> 2, c = idx & 3;
        cp16(bbase + swz(row, c), Bg + (size_t)(bn + row) * KP + kt * 32 + c * 8);
    }
    cp_commit();
}

__global__ void __launch_bounds__(256, 1)
gemm_vocab_mma(const __nv_bfloat16* __restrict__ Ag, const __nv_bfloat16* __restrict__ Bg,
               const float* __restrict__ bias, float* __restrict__ out, int m0) {
    extern __shared__ char sm[];
    uint32_t smb = smem_u32(sm);
    int tid = threadIdx.x;
    int wid = tid >> 5, lane = tid & 31;
    int wm = wid & 1, wn = wid >> 1;
    int bm = m0 + blockIdx.y * VBM, bn = blockIdx.x * VBN;

    int a_r = lane & 15;
    int a_c = lane >> 4;
    int b_r = (lane & 7) | (((lane >> 4) & 1) << 3);
    int b_c = (lane >> 3) & 1;

    float acc[4][8][4];
#pragma unroll
    for (int i = 0; i < 4; i++)
#pragma unroll
        for (int j = 0; j < 8; j++)
#pragma unroll
            for (int q = 0; q < 4; q++) acc[i][j][q] = 0.f;

    issue_tile(Ag, Bg, smb, 0, bm, bn, 0);
    issue_tile(Ag, Bg, smb, 1, bm, bn, 1);

    for (int kt = 0; kt < NKT; kt++) {
        cp_wait<1>();
        __syncthreads();
        if (kt + 2 < NKT) issue_tile(Ag, Bg, smb, (kt + 2) % NSTAGE, bm, bn, kt + 2);
        uint32_t abase = smb + (kt % NSTAGE) * STAGE_BYTES;
        uint32_t bbase = abase + ASZ;
#pragma unroll
        for (int s = 0; s < 2; s++) {
            uint32_t af[4][4], bf[4][4];
#pragma unroll
            for (int i = 0; i < 4; i++) {
                int row = wm * 64 + i * 16 + a_r;
                ldm_x4(af[i], abase + swz(row, s * 2 + a_c));
            }
#pragma unroll
            for (int jj = 0; jj < 4; jj++) {
                int row = wn * 64 + jj * 16 + b_r;
                ldm_x4(bf[jj], bbase + swz(row, s * 2 + b_c));
            }
#pragma unroll
            for (int i = 0; i < 4; i++)
#pragma unroll
                for (int jj = 0; jj < 4; jj++) {
                    mma_bf16(acc[i][2 * jj], af[i], bf[jj][0], bf[jj][1]);
                    mma_bf16(acc[i][2 * jj + 1], af[i], bf[jj][2], bf[jj][3]);
                }
        }
        __syncthreads();
    }

#pragma unroll
    for (int i = 0; i < 4; i++) {
#pragma unroll
        for (int j = 0; j < 8; j++) {
            int gm0 = bm + wm * 64 + i * 16 + (lane >> 2);
            int gn = bn + wn * 64 + j * 8 + 2 * (lane & 3);
#pragma unroll
            for (int h = 0; h < 2; h++) {
                int gm = gm0 + h * 8;
                int t = gm >> 8, b = gm & 255;
                float* row = out + ((size_t)b * TT + t) * VV;
                float c0 = acc[i][j][2 * h], c1 = acc[i][j][2 * h + 1];
                if (gn < VV) row[gn] = c0 + bias[gn];
                if (gn + 1 < VV) row[gn + 1] = c1 + bias[gn + 1];
            }
        }
    }
}

// ---------------- host launch --------------------------------------------------
extern "C" void kernel_launch(void* const* d_in, const int* in_sizes, int n_in,
                              void* d_out, int out_size) {
    const float* enc     = (const float*)d_in[0];
    const float* wv      = (const float*)d_in[1];
    const float* attn_W  = (const float*)d_in[2];
    const float* attn_b  = (const float*)d_in[3];
    const float* comb_W  = (const float*)d_in[4];
    const float* comb_b  = (const float*)d_in[5];
    const float* gate_W  = (const float*)d_in[6];
    const float* gate_b  = (const float*)d_in[7];
    const float* Wih     = (const float*)d_in[8];
    const float* Whh     = (const float*)d_in[9];
    const float* bih     = (const float*)d_in[10];
    const float* bhh     = (const float*)d_in[11];
    const float* vocab_W = (const float*)d_in[12];
    const float* vocab_b = (const float*)d_in[13];
    float* out = (float*)d_out;

    __nv_bfloat16 *p_Aattn, *p_Acomb, *p_ap, *p_wp;
    cudaGetSymbolAddress((void**)&p_Aattn, g_Aattn);
    cudaGetSymbolAddress((void**)&p_Acomb, g_Acomb);
    cudaGetSymbolAddress((void**)&p_ap, g_ap);
    cudaGetSymbolAddress((void**)&p_wp, g_wp);

    cudaFuncSetAttribute(gemm_vocab_mma, cudaFuncAttributeMaxDynamicSharedMemorySize, VSMEM);

    // side stream + events, created once (host-side resources only)
    static cudaStream_t s_side = nullptr;
    static cudaEvent_t s_ev[8];
    static cudaEvent_t s_evd;
    if (!s_side) {
        cudaStreamCreateWithFlags(&s_side, cudaStreamNonBlocking);
        for (int i = 0; i < 8; i++)
            cudaEventCreateWithFlags(&s_ev[i], cudaEventDisableTiming);
        cudaEventCreateWithFlags(&s_evd, cudaEventDisableTiming);
    }

    zero_all_kernel<<<1024, 256>>>();
    setup_x2_kernel<<<(TT * BB * WVV + 255) / 256, 256>>>(wv);
    {
        long total = (long)NW0 + NW1 + NW2 + NW3;
        setup_weights_kernel<<<(unsigned)((total + 255) / 256), 256>>>(
            attn_W, gate_W, comb_W, Wih, Whh, bih, bhh, vocab_W);
    }

    // vocab batches: after step 'last', project rows for steps [first, last].
    // Early batches are big (full-machine waves); tail is tapered to limit
    // exposed time after the loop ends.
    const int batch_last[5]  = {4, 9, 14, 17, 19};
    const int batch_first[5] = {0, 5, 10, 15, 18};
    int bi = 0;

    for (int t = 0; t < TT; t++) {
        const __nv_bfloat16* Aat = p_Aattn + (size_t)t * BB * LKP;
        __nv_bfloat16* Aco = p_Acomb + (size_t)t * BB * LKP;
        k_p1<<<48 * SPL, 256>>>(Aat);
        k_p2<<<BB, 256>>>(enc, attn_b, gate_b, Aco);
        k_p3<<<20 * SPL, 256>>>(Aco);
        k_p3b<<<(BB * WVV + 255) / 256, 256>>>(comb_b);
        k_p4<<<128 * SPL, 256>>>();
        __nv_bfloat16* Anext = (t + 1 < TT) ? (p_Aattn + (size_t)(t + 1) * BB * LKP) : (__nv_bfloat16*)nullptr;
        k_p5<<<512, 256>>>(t, Anext);
        if (bi < 5 && t == batch_last[bi]) {
            int m0 = batch_first[bi] * BB;
            int rows = (batch_last[bi] - batch_first[bi] + 1) * BB;
            cudaEventRecord(s_ev[bi], 0);
            cudaStreamWaitEvent(s_side, s_ev[bi], 0);
            gemm_vocab_mma<<<dim3(NPAD / VBN, rows / VBM), 256, VSMEM, s_side>>>(
                p_ap, p_wp, vocab_b, out, m0);
            bi++;
        }
    }
    // join side stream back into the main stream
    cudaEventRecord(s_evd, s_side);
    cudaStreamWaitEvent(0, s_evd, 0);
}

// round 12
// speedup vs baseline: 1.1172x; 1.1172x over previous
#include <cuda_runtime.h>
#include <cuda_bf16.h>
#include <cuda_fp16.h>
#include <cstdint>

#define BB 256
#define TT 20
#define HH 512
#define WVV 301
#define FF 196
#define CC 512
#define VV 9871
#define XK 813
#define NAG 708

#define KSEC 832          // padded K section (>=813, mult of 32)
#define LKP 2496          // 3 * KSEC
#define SPL 6             // split-K slices
#define KCH 416           // K per slice = LKP / SPL
#define NITS 13           // 416 / 32

#define KP2 512           // vocab K (single fp16 term)
#define NPAD 9984
#define MROWS (TT * BB)   // 5120

// ---------------- device globals ------------------------------------------------
__device__ __nv_bfloat16 g_Aattn[(size_t)TT * BB * LKP];  // [x|h] hi/hi/lo triple
__device__ __nv_bfloat16 g_Acomb[(size_t)TT * BB * LKP];  // [x|ctx]
__device__ __nv_bfloat16 g_Aih[(size_t)BB * LKP];         // [inp|h]
__device__ __nv_bfloat16 g_Wag2[(size_t)768 * LKP];       // [Whi|Wlo|Whi]
__device__ __nv_bfloat16 g_Wcomb2[(size_t)320 * LKP];
__device__ __nv_bfloat16 g_Wl2[(size_t)2048 * LKP];
__device__ float g_ag_s[SPL * BB * 768];     // attn+gate logit slices
__device__ float g_comb_s[SPL * BB * 320];   // comb raw slices (padded N=320)
__device__ float g_gate_s[SPL * BB * 2048];  // lstm gate slices
__device__ float g_cst[BB * HH];             // cell state
__device__ float g_bl[2048];                 // bih + bhh
__device__ __half g_ap2[(size_t)MROWS * KP2];  // vocab A (fp16 h)
__device__ __half g_wp2[(size_t)NPAD * KP2];   // vocab W (fp16)

// ---------------- common helpers ------------------------------------------------
__device__ __forceinline__ uint32_t smem_u32(const void* p) {
    uint32_t a;
    asm("{ .reg .u64 t; cvta.to.shared.u64 t, %1; cvt.u32.u64 %0, t; }" : "=r"(a) : "l"(p));
    return a;
}
__device__ __forceinline__ void cp16(uint32_t saddr, const void* gptr) {
    asm volatile("cp.async.cg.shared.global [%0], [%1], 16;" :: "r"(saddr), "l"(gptr));
}
__device__ __forceinline__ void cp_commit() { asm volatile("cp.async.commit_group;"); }
template <int N>
__device__ __forceinline__ void cp_wait() { asm volatile("cp.async.wait_group %0;" :: "n"(N)); }
__device__ __forceinline__ void ldm_x4(uint32_t* r, uint32_t addr) {
    asm volatile("ldmatrix.sync.aligned.m8n8.x4.shared.b16 {%0,%1,%2,%3}, [%4];"
                 : "=r"(r[0]), "=r"(r[1]), "=r"(r[2]), "=r"(r[3]) : "r"(addr));
}
__device__ __forceinline__ void mma_bf16(float* c, const uint32_t* a, uint32_t b0, uint32_t b1) {
    asm volatile(
        "mma.sync.aligned.m16n8k16.row.col.f32.bf16.bf16.f32 "
        "{%0,%1,%2,%3}, {%4,%5,%6,%7}, {%8,%9}, {%0,%1,%2,%3};"
        : "+f"(c[0]), "+f"(c[1]), "+f"(c[2]), "+f"(c[3])
        : "r"(a[0]), "r"(a[1]), "r"(a[2]), "r"(a[3]), "r"(b0), "r"(b1));
}
__device__ __forceinline__ void mma_fp16(float* c, const uint32_t* a, uint32_t b0, uint32_t b1) {
    asm volatile(
        "mma.sync.aligned.m16n8k16.row.col.f32.f16.f16.f32 "
        "{%0,%1,%2,%3}, {%4,%5,%6,%7}, {%8,%9}, {%0,%1,%2,%3};"
        : "+f"(c[0]), "+f"(c[1]), "+f"(c[2]), "+f"(c[3])
        : "r"(a[0]), "r"(a[1]), "r"(a[2]), "r"(a[3]), "r"(b0), "r"(b1));
}
// 64B-row swizzle for BK=32 tiles
__device__ __forceinline__ uint32_t swz(int row, int c) {
    return (uint32_t)(row * 64 + ((c ^ ((row >> 1) & 3)) * 16));
}
__device__ __forceinline__ void split_bf16(float v, __nv_bfloat16& hi, __nv_bfloat16& lo) {
    hi = __float2bfloat16(v);
    lo = __float2bfloat16(v - __bfloat162float(hi));
}

// 64x64 tile bf16 GEMM over NIT k-chunks of 32 starting at koff.
// 6-stage cp.async pipeline, 5 groups in flight. blockDim = 256. (R7 proven)
template <int NIT>
__device__ __forceinline__ void tile_mma(const __nv_bfloat16* __restrict__ Ag,
                                         const __nv_bfloat16* __restrict__ Bg,
                                         int bm, int bn, int koff, char* spipe,
                                         float acc[4][4]) {
    uint32_t smb = smem_u32(spipe);
    int tid = threadIdx.x;
    int wid = tid >> 5, lane = tid & 31;
    int wm = wid & 3, wn = wid >> 2;
    int a_r = lane & 15, a_c = lane >> 4;
    int b_r = (lane & 7) | (((lane >> 4) & 1) << 3);
    int b_c = (lane >> 3) & 1;
    int lrow = tid >> 2, lc = tid & 3;
#pragma unroll
    for (int q = 0; q < 4; q++)
#pragma unroll
        for (int j = 0; j < 4; j++) acc[q][j] = 0.f;

    const __nv_bfloat16* Abase = Ag + (size_t)(bm + lrow) * LKP + koff + lc * 8;
    const __nv_bfloat16* Bbase = Bg + (size_t)(bn + lrow) * LKP + koff + lc * 8;

#pragma unroll
    for (int st = 0; st < 5; st++) {
        if (st < NIT) {
            uint32_t ab = smb + st * 8192;
            cp16(ab + swz(lrow, lc), Abase + st * 32);
            cp16(ab + 4096 + swz(lrow, lc), Bbase + st * 32);
        }
        cp_commit();
    }
    for (int kt = 0; kt < NIT; kt++) {
        cp_wait<4>();
        __syncthreads();
        int nx = kt + 5;
        if (nx < NIT) {
            uint32_t ab = smb + (nx % 6) * 8192;
            cp16(ab + swz(lrow, lc), Abase + (size_t)nx * 32);
            cp16(ab + 4096 + swz(lrow, lc), Bbase + (size_t)nx * 32);
        }
        cp_commit();
        uint32_t ab = smb + (kt % 6) * 8192;
        uint32_t bb = ab + 4096;
#pragma unroll
        for (int s = 0; s < 2; s++) {
            uint32_t af[4];
            ldm_x4(af, ab + swz(wm * 16 + a_r, s * 2 + a_c));
#pragma unroll
            for (int jj = 0; jj < 2; jj++) {
                uint32_t bf[4];
                ldm_x4(bf, bb + swz(wn * 32 + jj * 16 + b_r, s * 2 + b_c));
                mma_bf16(acc[2 * jj], af, bf[0], bf[1]);
                mma_bf16(acc[2 * jj + 1], af, bf[2], bf[3]);
            }
        }
        __syncthreads();
    }
}

// ---------------- setup kernels (3 launches before loop) ------------------------
__global__ void zero_all_kernel() {
    size_t stride = (size_t)gridDim.x * blockDim.x;
    size_t id = (size_t)blockIdx.x * blockDim.x + threadIdx.x;
    uint4 z = make_uint4(0, 0, 0, 0);
    uint4* pa = (uint4*)g_Aattn;
    size_t nA = sizeof(g_Aattn) / 16;
    for (size_t i = id; i < nA; i += stride) pa[i] = z;
    uint4* pc = (uint4*)g_Acomb;
    for (size_t i = id; i < nA; i += stride) pc[i] = z;
    uint4* pi = (uint4*)g_Aih;
    size_t nI = sizeof(g_Aih) / 16;
    for (size_t i = id; i < nI; i += stride) pi[i] = z;
    uint4* ps = (uint4*)g_cst;
    size_t nS = sizeof(g_cst) / 16;
    for (size_t i = id; i < nS; i += stride) ps[i] = z;
}

__global__ void setup_x2_kernel(const float* __restrict__ wv) {
    int idx = blockIdx.x * blockDim.x + threadIdx.x;
    const int total = TT * BB * WVV;
    if (idx >= total) return;
    int t = idx / (BB * WVV);
    int r = idx % (BB * WVV);
    int b = r / WVV, w = r % WVV;
    float v = (t == 0) ? 0.f : wv[(size_t)b * TT * WVV + (size_t)(t - 1) * WVV + w];
    __nv_bfloat16 hi, lo;
    split_bf16(v, hi, lo);
    size_t base = ((size_t)t * BB + b) * LKP;
    g_Aattn[base + w] = hi;
    g_Aattn[base + KSEC + w] = hi;
    g_Aattn[base + 2 * KSEC + w] = lo;
    g_Acomb[base + w] = hi;
    g_Acomb[base + KSEC + w] = hi;
    g_Acomb[base + 2 * KSEC + w] = lo;
}

// merged weight prep: wag2 | wcomb2 | wl2 | wp2(fp16) | bl
#define NW0 (768 * KSEC)
#define NW1 (320 * KSEC)
#define NW2 (2048 * KSEC)
#define NW3 (NPAD * HH)
__global__ void setup_weights_kernel(const float* __restrict__ attn_W,
                                     const float* __restrict__ gate_W,
                                     const float* __restrict__ comb_W,
                                     const float* __restrict__ Wih,
                                     const float* __restrict__ Whh,
                                     const float* __restrict__ bih,
                                     const float* __restrict__ bhh,
                                     const float* __restrict__ vw) {
    long idx = (long)blockIdx.x * blockDim.x + threadIdx.x;
    if (idx < 2048) g_bl[idx] = bih[idx] + bhh[idx];
    if (idx < NW0) {
        int n = idx / KSEC, k = idx % KSEC;
        float v = 0.f;
        if (k < XK) {
            if (n < FF) v = attn_W[(size_t)n * XK + k];
            else if (n < NAG && k >= WVV) v = gate_W[(size_t)(n - FF) * HH + (k - WVV)];
        }
        __nv_bfloat16 hi, lo;
        split_bf16(v, hi, lo);
        size_t base = (size_t)n * LKP;
        g_Wag2[base + k] = hi;
        g_Wag2[base + KSEC + k] = lo;
        g_Wag2[base + 2 * KSEC + k] = hi;
        return;
    }
    idx -= NW0;
    if (idx < NW1) {
        int n = idx / KSEC, k = idx % KSEC;
        float v = (n < WVV && k < XK) ? comb_W[(size_t)n * XK + k] : 0.f;
        __nv_bfloat16 hi, lo;
        split_bf16(v, hi, lo);
        size_t base = (size_t)n * LKP;
        g_Wcomb2[base + k] = hi;
        g_Wcomb2[base + KSEC + k] = lo;
        g_Wcomb2[base + 2 * KSEC + k] = hi;
        return;
    }
    idx -= NW1;
    if (idx < NW2) {
        int n = idx / KSEC, k = idx % KSEC;
        float v = 0.f;
        if (k < XK) v = (k < WVV) ? Wih[(size_t)n * WVV + k] : Whh[(size_t)n * HH + (k - WVV)];
        __nv_bfloat16 hi, lo;
        split_bf16(v, hi, lo);
        size_t base = (size_t)n * LKP;
        g_Wl2[base + k] = hi;
        g_Wl2[base + KSEC + k] = lo;
        g_Wl2[base + 2 * KSEC + k] = hi;
        return;
    }
    idx -= NW2;
    if (idx < NW3) {
        int n = idx / HH, k = idx % HH;
        float v = (n < VV) ? vw[(size_t)n * HH + k] : 0.f;
        g_wp2[(size_t)n * KP2 + k] = __float2half(v);
    }
}

// ---------------- loop kernels ---------------------------------------------------
// P1: attn+gate logits, split-K x6. grid = 288
__global__ void __launch_bounds__(256) k_p1(const __nv_bfloat16* __restrict__ A) {
    __shared__ __align__(16) char s_pipe[6 * 8192];
    float acc[4][4];
    int job = blockIdx.x;
    int z = job % SPL, tile = job / SPL;
    int bm = (tile / 12) * 64, bn = (tile % 12) * 64;
    tile_mma<NITS>(A, g_Wag2, bm, bn, z * KCH, s_pipe, acc);
    int tid = threadIdx.x, wid = tid >> 5, lane = tid & 31;
    float* dst = g_ag_s + (size_t)z * BB * 768;
    int r0 = bm + (wid & 3) * 16 + (lane >> 2);
    int c0 = bn + (wid >> 2) * 32 + 2 * (lane & 3);
#pragma unroll
    for (int q = 0; q < 4; q++)
#pragma unroll
        for (int h = 0; h < 2; h++) {
            dst[(r0 + 8 * h) * 768 + c0 + q * 8] = acc[q][2 * h];
            dst[(r0 + 8 * h) * 768 + c0 + q * 8 + 1] = acc[q][2 * h + 1];
        }
}

// P2: softmax + gated ctx (sums 6 slices). grid = BB
__global__ void __launch_bounds__(256)
k_p2(const float* __restrict__ enc, const float* __restrict__ attn_b,
     const float* __restrict__ gate_b, __nv_bfloat16* __restrict__ Acomb_t) {
    __shared__ float s_red[256];
    __shared__ __align__(16) float s_aw[196];
    int b = blockIdx.x;
    int tid = threadIdx.x;
    int wid = tid >> 5, lane = tid & 31;
    const float* pb = g_ag_s + (size_t)b * 768;
    float v = -3.0e38f;
    if (tid < FF) {
        v = attn_b[tid];
#pragma unroll
        for (int z = 0; z < SPL; z++) v += pb[(size_t)z * BB * 768 + tid];
    }
    s_red[tid] = v;
    __syncthreads();
    for (int s = 128; s > 0; s >>= 1) {
        if (tid < s) s_red[tid] = fmaxf(s_red[tid], s_red[tid + s]);
        __syncthreads();
    }
    float mx = s_red[0];
    __syncthreads();
    float e = (tid < FF) ? expf(v - mx) : 0.f;
    s_red[tid] = e;
    __syncthreads();
    for (int s = 128; s > 0; s >>= 1) {
        if (tid < s) s_red[tid] += s_red[tid + s];
        __syncthreads();
    }
    float inv = 1.f / s_red[0];
    __syncthreads();
    if (tid < FF) s_aw[tid] = e * inv;
    __syncthreads();
    const float4* sa4 = (const float4*)s_aw;
    const float4* encb = (const float4*)(enc + (size_t)b * CC * FF);
    size_t cbase = (size_t)b * LKP;
    for (int grp = 0; grp < 8; grp++) {
#pragma unroll
        for (int ci = 0; ci < 8; ci++) {
            int c = wid * 64 + grp * 8 + ci;
            const float4* row = encb + (size_t)c * 49;
            float4 a0 = sa4[lane];
            float4 v0 = row[lane];
            float sum = v0.x * a0.x + v0.y * a0.y + v0.z * a0.z + v0.w * a0.w;
            if (lane < 17) {
                float4 a1 = sa4[lane + 32];
                float4 v1 = row[lane + 32];
                sum += v1.x * a1.x + v1.y * a1.y + v1.z * a1.z + v1.w * a1.w;
            }
#pragma unroll
            for (int o = 16; o > 0; o >>= 1) sum += __shfl_xor_sync(0xffffffffu, sum, o);
            if (lane == 0) {
                float gz = gate_b[c];
#pragma unroll
                for (int z = 0; z < SPL; z++) gz += pb[(size_t)z * BB * 768 + FF + c];
                float gamma = 1.f / (1.f + expf(-gz));
                float val = gamma * sum;
                __nv_bfloat16 hi, lo;
                split_bf16(val, hi, lo);
                Acomb_t[cbase + WVV + c] = hi;
                Acomb_t[cbase + KSEC + WVV + c] = hi;
                Acomb_t[cbase + 2 * KSEC + WVV + c] = lo;
            }
        }
    }
}

// P3: comb gemm, split-K x6, slice output. grid = 120
__global__ void __launch_bounds__(256)
k_p3(const __nv_bfloat16* __restrict__ A) {
    __shared__ __align__(16) char s_pipe[6 * 8192];
    float acc[4][4];
    int job = blockIdx.x;
    int z = job % SPL, tile = job / SPL;
    int bm = (tile / 5) * 64, bn = (tile % 5) * 64;
    tile_mma<NITS>(A, g_Wcomb2, bm, bn, z * KCH, s_pipe, acc);
    int tid = threadIdx.x, wid = tid >> 5, lane = tid & 31;
    float* dst = g_comb_s + (size_t)z * BB * 320;
    int r0 = bm + (wid & 3) * 16 + (lane >> 2);
    int c0 = bn + (wid >> 2) * 32 + 2 * (lane & 3);
#pragma unroll
    for (int q = 0; q < 4; q++)
#pragma unroll
        for (int h = 0; h < 2; h++) {
            dst[(r0 + 8 * h) * 320 + c0 + q * 8] = acc[q][2 * h];
            dst[(r0 + 8 * h) * 320 + c0 + q * 8 + 1] = acc[q][2 * h + 1];
        }
}

// P3b: reduce 6 comb slices + bias + relu -> g_Aih triple. grid = 302
__global__ void __launch_bounds__(256)
k_p3b(const float* __restrict__ comb_b) {
    int idx = blockIdx.x * 256 + threadIdx.x;
    if (idx >= BB * WVV) return;
    int b = idx / WVV, w = idx % WVV;
    float s = comb_b[w];
#pragma unroll
    for (int z = 0; z < SPL; z++) s += g_comb_s[((size_t)z * BB + b) * 320 + w];
    s = fmaxf(s, 0.f);
    __nv_bfloat16 hi, lo;
    split_bf16(s, hi, lo);
    size_t ib = (size_t)b * LKP + w;
    g_Aih[ib] = hi;
    g_Aih[ib + KSEC] = hi;
    g_Aih[ib + 2 * KSEC] = lo;
}

// P4: lstm gates gemm, split-K x6, slice output. grid = 768
__global__ void __launch_bounds__(256) k_p4() {
    __shared__ __align__(16) char s_pipe[6 * 8192];
    float acc[4][4];
    int job = blockIdx.x;
    int z = job % SPL, tile = job / SPL;
    int bm = (tile / 32) * 64, bn = (tile % 32) * 64;
    tile_mma<NITS>(g_Aih, g_Wl2, bm, bn, z * KCH, s_pipe, acc);
    int tid = threadIdx.x, wid = tid >> 5, lane = tid & 31;
    float* dst = g_gate_s + (size_t)z * BB * 2048;
    int r0 = bm + (wid & 3) * 16 + (lane >> 2);
    int c0 = bn + (wid >> 2) * 32 + 2 * (lane & 3);
#pragma unroll
    for (int q = 0; q < 4; q++)
#pragma unroll
        for (int h = 0; h < 2; h++) {
            dst[(r0 + 8 * h) * 2048 + c0 + q * 8] = acc[q][2 * h];
            dst[(r0 + 8 * h) * 2048 + c0 + q * 8 + 1] = acc[q][2 * h + 1];
        }
}

// P5: LSTM cell elementwise, sums 6 gate slices. grid = 512
__global__ void __launch_bounds__(256)
k_p5(int t, __nv_bfloat16* __restrict__ Aattn_next) {
    int idx = blockIdx.x * 256 + threadIdx.x;
    int b = idx >> 9, j = idx & 511;
    size_t gb = (size_t)b * 2048;
    float i_ = g_bl[j], f_ = g_bl[512 + j], g_ = g_bl[1024 + j], o_ = g_bl[1536 + j];
#pragma unroll
    for (int z = 0; z < SPL; z++) {
        const float* gr = g_gate_s + (size_t)z * BB * 2048 + gb;
        i_ += gr[j];
        f_ += gr[512 + j];
        g_ += gr[1024 + j];
        o_ += gr[1536 + j];
    }
    float si = 1.f / (1.f + expf(-i_));
    float sf = 1.f / (1.f + expf(-f_));
    float so = 1.f / (1.f + expf(-o_));
    float cn = sf * g_cst[idx] + si * tanhf(g_);
    float hn = so * tanhf(cn);
    g_cst[idx] = cn;
    __nv_bfloat16 hi, lo;
    split_bf16(hn, hi, lo);
    size_t ib = (size_t)b * LKP + WVV + j;
    g_Aih[ib] = hi;
    g_Aih[ib + KSEC] = hi;
    g_Aih[ib + 2 * KSEC] = lo;
    if (Aattn_next) {
        size_t ab = (size_t)b * LKP + WVV + j;
        Aattn_next[ab] = hi;
        Aattn_next[ab + KSEC] = hi;
        Aattn_next[ab + 2 * KSEC] = lo;
    }
    // vocab A row (single fp16 term)
    g_ap2[((size_t)t * BB + b) * KP2 + j] = __float2half(hn);
}

// ===================== vocab GEMM (fp16 single-term, per-step slices) ===========
#define VBM 128
#define VBN 256
#define NKT2 (KP2 / 32)    // 16
#define STAGE_BYTES 24576
#define ASZ 8192
#define NSTAGE 3
#define VSMEM (NSTAGE * STAGE_BYTES)

__device__ __forceinline__ void issue_tile(const __half* __restrict__ Ag,
                                           const __half* __restrict__ Bg,
                                           uint32_t smb, int stage, int bm, int bn, int kt) {
    int tid = threadIdx.x;
    uint32_t abase = smb + stage * STAGE_BYTES;
    uint32_t bbase = abase + ASZ;
#pragma unroll
    for (int l = 0; l < 2; l++) {
        int idx = tid + 256 * l;
        int row = idx >> 2, c = idx & 3;
        cp16(abase + swz(row, c), Ag + (size_t)(bm + row) * KP2 + kt * 32 + c * 8);
    }
#pragma unroll
    for (int l = 0; l < 4; l++) {
        int idx = tid + 256 * l;
        int row = idx >> 2, c = idx & 3;
        cp16(bbase + swz(row, c), Bg + (size_t)(bn + row) * KP2 + kt * 32 + c * 8);
    }
    cp_commit();
}

__global__ void __launch_bounds__(256, 1)
gemm_vocab_mma(const __half* __restrict__ Ag, const __half* __restrict__ Bg,
               const float* __restrict__ bias, float* __restrict__ out, int m0) {
    extern __shared__ char sm[];
    uint32_t smb = smem_u32(sm);
    int tid = threadIdx.x;
    int wid = tid >> 5, lane = tid & 31;
    int wm = wid & 1, wn = wid >> 1;
    int bm = m0 + blockIdx.y * VBM, bn = blockIdx.x * VBN;

    int a_r = lane & 15;
    int a_c = lane >> 4;
    int b_r = (lane & 7) | (((lane >> 4) & 1) << 3);
    int b_c = (lane >> 3) & 1;

    float acc[4][8][4];
#pragma unroll
    for (int i = 0; i < 4; i++)
#pragma unroll
        for (int j = 0; j < 8; j++)
#pragma unroll
            for (int q = 0; q < 4; q++) acc[i][j][q] = 0.f;

    issue_tile(Ag, Bg, smb, 0, bm, bn, 0);
    issue_tile(Ag, Bg, smb, 1, bm, bn, 1);

    for (int kt = 0; kt < NKT2; kt++) {
        cp_wait<1>();
        __syncthreads();
        if (kt + 2 < NKT2) issue_tile(Ag, Bg, smb, (kt + 2) % NSTAGE, bm, bn, kt + 2);
        uint32_t abase = smb + (kt % NSTAGE) * STAGE_BYTES;
        uint32_t bbase = abase + ASZ;
#pragma unroll
        for (int s = 0; s < 2; s++) {
            uint32_t af[4][4], bf[4][4];
#pragma unroll
            for (int i = 0; i < 4; i++) {
                int row = wm * 64 + i * 16 + a_r;
                ldm_x4(af[i], abase + swz(row, s * 2 + a_c));
            }
#pragma unroll
            for (int jj = 0; jj < 4; jj++) {
                int row = wn * 64 + jj * 16 + b_r;
                ldm_x4(bf[jj], bbase + swz(row, s * 2 + b_c));
            }
#pragma unroll
            for (int i = 0; i < 4; i++)
#pragma unroll
                for (int jj = 0; jj < 4; jj++) {
                    mma_fp16(acc[i][2 * jj], af[i], bf[jj][0], bf[jj][1]);
                    mma_fp16(acc[i][2 * jj + 1], af[i], bf[jj][2], bf[jj][3]);
                }
        }
        __syncthreads();
    }

#pragma unroll
    for (int i = 0; i < 4; i++) {
#pragma unroll
        for (int j = 0; j < 8; j++) {
            int gm0 = bm + wm * 64 + i * 16 + (lane >> 2);
            int gn = bn + wn * 64 + j * 8 + 2 * (lane & 3);
#pragma unroll
            for (int h = 0; h < 2; h++) {
                int gm = gm0 + h * 8;
                int t = gm >> 8, b = gm & 255;
                float* row = out + ((size_t)b * TT + t) * VV;
                float c0 = acc[i][j][2 * h], c1 = acc[i][j][2 * h + 1];
                if (gn < VV) row[gn] = c0 + bias[gn];
                if (gn + 1 < VV) row[gn + 1] = c1 + bias[gn + 1];
            }
        }
    }
}

// ---------------- host launch --------------------------------------------------
extern "C" void kernel_launch(void* const* d_in, const int* in_sizes, int n_in,
                              void* d_out, int out_size) {
    const float* enc     = (const float*)d_in[0];
    const float* wv      = (const float*)d_in[1];
    const float* attn_W  = (const float*)d_in[2];
    const float* attn_b  = (const float*)d_in[3];
    const float* comb_W  = (const float*)d_in[4];
    const float* comb_b  = (const float*)d_in[5];
    const float* gate_W  = (const float*)d_in[6];
    const float* gate_b  = (const float*)d_in[7];
    const float* Wih     = (const float*)d_in[8];
    const float* Whh     = (const float*)d_in[9];
    const float* bih     = (const float*)d_in[10];
    const float* bhh     = (const float*)d_in[11];
    const float* vocab_W = (const float*)d_in[12];
    const float* vocab_b = (const float*)d_in[13];
    float* out = (float*)d_out;

    __nv_bfloat16 *p_Aattn, *p_Acomb;
    __half *p_ap2, *p_wp2;
    cudaGetSymbolAddress((void**)&p_Aattn, g_Aattn);
    cudaGetSymbolAddress((void**)&p_Acomb, g_Acomb);
    cudaGetSymbolAddress((void**)&p_ap2, g_ap2);
    cudaGetSymbolAddress((void**)&p_wp2, g_wp2);

    cudaFuncSetAttribute(gemm_vocab_mma, cudaFuncAttributeMaxDynamicSharedMemorySize, VSMEM);

    // side stream + events, created once (host-side resources only)
    static cudaStream_t s_side = nullptr;
    static cudaEvent_t s_ev[TT];
    static cudaEvent_t s_evd;
    if (!s_side) {
        cudaStreamCreateWithFlags(&s_side, cudaStreamNonBlocking);
        for (int t = 0; t < TT; t++)
            cudaEventCreateWithFlags(&s_ev[t], cudaEventDisableTiming);
        cudaEventCreateWithFlags(&s_evd, cudaEventDisableTiming);
    }

    zero_all_kernel<<<1024, 256>>>();
    setup_x2_kernel<<<(TT * BB * WVV + 255) / 256, 256>>>(wv);
    {
        long total = (long)NW0 + NW1 + NW2 + NW3;
        setup_weights_kernel<<<(unsigned)((total + 255) / 256), 256>>>(
            attn_W, gate_W, comb_W, Wih, Whh, bih, bhh, vocab_W);
    }

    for (int t = 0; t < TT; t++) {
        const __nv_bfloat16* Aat = p_Aattn + (size_t)t * BB * LKP;
        __nv_bfloat16* Aco = p_Acomb + (size_t)t * BB * LKP;
        k_p1<<<48 * SPL, 256>>>(Aat);
        k_p2<<<BB, 256>>>(enc, attn_b, gate_b, Aco);
        k_p3<<<20 * SPL, 256>>>(Aco);
        k_p3b<<<(BB * WVV + 255) / 256, 256>>>(comb_b);
        k_p4<<<128 * SPL, 256>>>();
        __nv_bfloat16* Anext = (t + 1 < TT) ? (p_Aattn + (size_t)(t + 1) * BB * LKP) : (__nv_bfloat16*)nullptr;
        k_p5<<<512, 256>>>(t, Anext);
        // fork: vocab slice for this timestep on the side stream
        cudaEventRecord(s_ev[t], 0);
        cudaStreamWaitEvent(s_side, s_ev[t], 0);
        gemm_vocab_mma<<<dim3(NPAD / VBN, BB / VBM), 256, VSMEM, s_side>>>(
            p_ap2, p_wp2, vocab_b, out, t * BB);
    }
    // join side stream back into the main stream
    cudaEventRecord(s_evd, s_side);
    cudaStreamWaitEvent(0, s_evd, 0);
}

// round 14
// speedup vs baseline: 1.1321x; 1.0133x over previous
#include <cuda_runtime.h>
#include <cuda_bf16.h>
#include <cuda_fp16.h>
#include <cstdint>

#define BB 256
#define TT 20
#define HH 512
#define WVV 301
#define FF 196
#define CC 512
#define VV 9871
#define XK 813
#define NAG 708

#define KSEC 832          // padded K section (>=813, mult of 32)
#define LKP 2496          // 3 * KSEC
#define SPL 6             // split-K slices
#define KCH 416           // K per slice = LKP / SPL
#define NITS 13           // 416 / 32

#define KP2 512           // vocab K (single fp16 term)
#define NPAD 9984
#define MROWS (TT * BB)   // 5120

// ---------------- device globals ------------------------------------------------
__device__ __nv_bfloat16 g_Aattn[(size_t)TT * BB * LKP];  // [x|h] hi/hi/lo triple
__device__ __nv_bfloat16 g_Acomb[(size_t)TT * BB * LKP];  // [x|ctx]
__device__ __nv_bfloat16 g_Aih[(size_t)BB * LKP];         // [inp|h]
__device__ __nv_bfloat16 g_Wag2[(size_t)768 * LKP];       // [Whi|Wlo|Whi]
__device__ __nv_bfloat16 g_Wcomb2[(size_t)320 * LKP];
__device__ __nv_bfloat16 g_Wl2[(size_t)2048 * LKP];
__device__ float g_ag_s[SPL * BB * 768];     // attn+gate logit slices
__device__ float g_comb_s[SPL * BB * 320];   // comb raw slices (padded N=320)
__device__ float g_gate_s[SPL * BB * 2048];  // lstm gate slices
__device__ float g_cst[BB * HH];             // cell state
__device__ float g_bl[2048];                 // bih + bhh
__device__ __half g_ap2[(size_t)MROWS * KP2];  // vocab A (fp16 h)
__device__ __half g_wp2[(size_t)NPAD * KP2];   // vocab W (fp16)

// ---------------- common helpers ------------------------------------------------
__device__ __forceinline__ uint32_t smem_u32(const void* p) {
    uint32_t a;
    asm("{ .reg .u64 t; cvta.to.shared.u64 t, %1; cvt.u32.u64 %0, t; }" : "=r"(a) : "l"(p));
    return a;
}
__device__ __forceinline__ void cp16(uint32_t saddr, const void* gptr) {
    asm volatile("cp.async.cg.shared.global [%0], [%1], 16;" :: "r"(saddr), "l"(gptr));
}
__device__ __forceinline__ void cp_commit() { asm volatile("cp.async.commit_group;"); }
template <int N>
__device__ __forceinline__ void cp_wait() { asm volatile("cp.async.wait_group %0;" :: "n"(N)); }
__device__ __forceinline__ void ldm_x4(uint32_t* r, uint32_t addr) {
    asm volatile("ldmatrix.sync.aligned.m8n8.x4.shared.b16 {%0,%1,%2,%3}, [%4];"
                 : "=r"(r[0]), "=r"(r[1]), "=r"(r[2]), "=r"(r[3]) : "r"(addr));
}
__device__ __forceinline__ void mma_bf16(float* c, const uint32_t* a, uint32_t b0, uint32_t b1) {
    asm volatile(
        "mma.sync.aligned.m16n8k16.row.col.f32.bf16.bf16.f32 "
        "{%0,%1,%2,%3}, {%4,%5,%6,%7}, {%8,%9}, {%0,%1,%2,%3};"
        : "+f"(c[0]), "+f"(c[1]), "+f"(c[2]), "+f"(c[3])
        : "r"(a[0]), "r"(a[1]), "r"(a[2]), "r"(a[3]), "r"(b0), "r"(b1));
}
__device__ __forceinline__ void mma_fp16(float* c, const uint32_t* a, uint32_t b0, uint32_t b1) {
    asm volatile(
        "mma.sync.aligned.m16n8k16.row.col.f32.f16.f16.f32 "
        "{%0,%1,%2,%3}, {%4,%5,%6,%7}, {%8,%9}, {%0,%1,%2,%3};"
        : "+f"(c[0]), "+f"(c[1]), "+f"(c[2]), "+f"(c[3])
        : "r"(a[0]), "r"(a[1]), "r"(a[2]), "r"(a[3]), "r"(b0), "r"(b1));
}
// 64B-row swizzle for BK=32 tiles
__device__ __forceinline__ uint32_t swz(int row, int c) {
    return (uint32_t)(row * 64 + ((c ^ ((row >> 1) & 3)) * 16));
}
__device__ __forceinline__ void split_bf16(float v, __nv_bfloat16& hi, __nv_bfloat16& lo) {
    hi = __float2bfloat16(v);
    lo = __float2bfloat16(v - __bfloat162float(hi));
}

// 64x64 tile bf16 GEMM over NIT k-chunks of 32 starting at koff.
// 6-stage cp.async pipeline, 5 groups in flight. blockDim = 256.
template <int NIT>
__device__ __forceinline__ void tile_mma(const __nv_bfloat16* __restrict__ Ag,
                                         const __nv_bfloat16* __restrict__ Bg,
                                         int bm, int bn, int koff, char* spipe,
                                         float acc[4][4]) {
    uint32_t smb = smem_u32(spipe);
    int tid = threadIdx.x;
    int wid = tid >> 5, lane = tid & 31;
    int wm = wid & 3, wn = wid >> 2;
    int a_r = lane & 15, a_c = lane >> 4;
    int b_r = (lane & 7) | (((lane >> 4) & 1) << 3);
    int b_c = (lane >> 3) & 1;
    int lrow = tid >> 2, lc = tid & 3;
#pragma unroll
    for (int q = 0; q < 4; q++)
#pragma unroll
        for (int j = 0; j < 4; j++) acc[q][j] = 0.f;

    const __nv_bfloat16* Abase = Ag + (size_t)(bm + lrow) * LKP + koff + lc * 8;
    const __nv_bfloat16* Bbase = Bg + (size_t)(bn + lrow) * LKP + koff + lc * 8;

#pragma unroll
    for (int st = 0; st < 5; st++) {
        if (st < NIT) {
            uint32_t ab = smb + st * 8192;
            cp16(ab + swz(lrow, lc), Abase + st * 32);
            cp16(ab + 4096 + swz(lrow, lc), Bbase + st * 32);
        }
        cp_commit();
    }
    for (int kt = 0; kt < NIT; kt++) {
        cp_wait<4>();
        __syncthreads();
        int nx = kt + 5;
        if (nx < NIT) {
            uint32_t ab = smb + (nx % 6) * 8192;
            cp16(ab + swz(lrow, lc), Abase + (size_t)nx * 32);
            cp16(ab + 4096 + swz(lrow, lc), Bbase + (size_t)nx * 32);
        }
        cp_commit();
        uint32_t ab = smb + (kt % 6) * 8192;
        uint32_t bb = ab + 4096;
#pragma unroll
        for (int s = 0; s < 2; s++) {
            uint32_t af[4];
            ldm_x4(af, ab + swz(wm * 16 + a_r, s * 2 + a_c));
#pragma unroll
            for (int jj = 0; jj < 2; jj++) {
                uint32_t bf[4];
                ldm_x4(bf, bb + swz(wn * 32 + jj * 16 + b_r, s * 2 + b_c));
                mma_bf16(acc[2 * jj], af, bf[0], bf[1]);
                mma_bf16(acc[2 * jj + 1], af, bf[2], bf[3]);
            }
        }
        __syncthreads();
    }
}

// ---------------- setup kernels (3 launches before loop) ------------------------
__global__ void zero_all_kernel() {
    size_t stride = (size_t)gridDim.x * blockDim.x;
    size_t id = (size_t)blockIdx.x * blockDim.x + threadIdx.x;
    uint4 z = make_uint4(0, 0, 0, 0);
    uint4* pa = (uint4*)g_Aattn;
    size_t nA = sizeof(g_Aattn) / 16;
    for (size_t i = id; i < nA; i += stride) pa[i] = z;
    uint4* pc = (uint4*)g_Acomb;
    for (size_t i = id; i < nA; i += stride) pc[i] = z;
    uint4* pi = (uint4*)g_Aih;
    size_t nI = sizeof(g_Aih) / 16;
    for (size_t i = id; i < nI; i += stride) pi[i] = z;
    uint4* ps = (uint4*)g_cst;
    size_t nS = sizeof(g_cst) / 16;
    for (size_t i = id; i < nS; i += stride) ps[i] = z;
}

__global__ void setup_x2_kernel(const float* __restrict__ wv) {
    int idx = blockIdx.x * blockDim.x + threadIdx.x;
    const int total = TT * BB * WVV;
    if (idx >= total) return;
    int t = idx / (BB * WVV);
    int r = idx % (BB * WVV);
    int b = r / WVV, w = r % WVV;
    float v = (t == 0) ? 0.f : wv[(size_t)b * TT * WVV + (size_t)(t - 1) * WVV + w];
    __nv_bfloat16 hi, lo;
    split_bf16(v, hi, lo);
    size_t base = ((size_t)t * BB + b) * LKP;
    g_Aattn[base + w] = hi;
    g_Aattn[base + KSEC + w] = hi;
    g_Aattn[base + 2 * KSEC + w] = lo;
    g_Acomb[base + w] = hi;
    g_Acomb[base + KSEC + w] = hi;
    g_Acomb[base + 2 * KSEC + w] = lo;
}

// merged weight prep: wag2 | wcomb2 | wl2 | wp2(fp16) | bl
#define NW0 (768 * KSEC)
#define NW1 (320 * KSEC)
#define NW2 (2048 * KSEC)
#define NW3 (NPAD * HH)
__global__ void setup_weights_kernel(const float* __restrict__ attn_W,
                                     const float* __restrict__ gate_W,
                                     const float* __restrict__ comb_W,
                                     const float* __restrict__ Wih,
                                     const float* __restrict__ Whh,
                                     const float* __restrict__ bih,
                                     const float* __restrict__ bhh,
                                     const float* __restrict__ vw) {
    long idx = (long)blockIdx.x * blockDim.x + threadIdx.x;
    if (idx < 2048) g_bl[idx] = bih[idx] + bhh[idx];
    if (idx < NW0) {
        int n = idx / KSEC, k = idx % KSEC;
        float v = 0.f;
        if (k < XK) {
            if (n < FF) v = attn_W[(size_t)n * XK + k];
            else if (n < NAG && k >= WVV) v = gate_W[(size_t)(n - FF) * HH + (k - WVV)];
        }
        __nv_bfloat16 hi, lo;
        split_bf16(v, hi, lo);
        size_t base = (size_t)n * LKP;
        g_Wag2[base + k] = hi;
        g_Wag2[base + KSEC + k] = lo;
        g_Wag2[base + 2 * KSEC + k] = hi;
        return;
    }
    idx -= NW0;
    if (idx < NW1) {
        int n = idx / KSEC, k = idx % KSEC;
        float v = (n < WVV && k < XK) ? comb_W[(size_t)n * XK + k] : 0.f;
        __nv_bfloat16 hi, lo;
        split_bf16(v, hi, lo);
        size_t base = (size_t)n * LKP;
        g_Wcomb2[base + k] = hi;
        g_Wcomb2[base + KSEC + k] = lo;
        g_Wcomb2[base + 2 * KSEC + k] = hi;
        return;
    }
    idx -= NW1;
    if (idx < NW2) {
        int n = idx / KSEC, k = idx % KSEC;
        float v = 0.f;
        if (k < XK) v = (k < WVV) ? Wih[(size_t)n * WVV + k] : Whh[(size_t)n * HH + (k - WVV)];
        __nv_bfloat16 hi, lo;
        split_bf16(v, hi, lo);
        size_t base = (size_t)n * LKP;
        g_Wl2[base + k] = hi;
        g_Wl2[base + KSEC + k] = lo;
        g_Wl2[base + 2 * KSEC + k] = hi;
        return;
    }
    idx -= NW2;
    if (idx < NW3) {
        int n = idx / HH, k = idx % HH;
        float v = (n < VV) ? vw[(size_t)n * HH + k] : 0.f;
        g_wp2[(size_t)n * KP2 + k] = __float2half(v);
    }
}

// ---------------- loop kernels ---------------------------------------------------
// P1: attn+gate logits, split-K x6. grid = 288
__global__ void __launch_bounds__(256) k_p1(const __nv_bfloat16* __restrict__ A) {
    __shared__ __align__(16) char s_pipe[6 * 8192];
    float acc[4][4];
    int job = blockIdx.x;
    int z = job % SPL, tile = job / SPL;
    int bm = (tile / 12) * 64, bn = (tile % 12) * 64;
    tile_mma<NITS>(A, g_Wag2, bm, bn, z * KCH, s_pipe, acc);
    int tid = threadIdx.x, wid = tid >> 5, lane = tid & 31;
    float* dst = g_ag_s + (size_t)z * BB * 768;
    int r0 = bm + (wid & 3) * 16 + (lane >> 2);
    int c0 = bn + (wid >> 2) * 32 + 2 * (lane & 3);
#pragma unroll
    for (int q = 0; q < 4; q++)
#pragma unroll
        for (int h = 0; h < 2; h++) {
            dst[(r0 + 8 * h) * 768 + c0 + q * 8] = acc[q][2 * h];
            dst[(r0 + 8 * h) * 768 + c0 + q * 8 + 1] = acc[q][2 * h + 1];
        }
}

// P2: softmax + gated ctx (sums 6 slices). grid = BB
__global__ void __launch_bounds__(256)
k_p2(const float* __restrict__ enc, const float* __restrict__ attn_b,
     const float* __restrict__ gate_b, __nv_bfloat16* __restrict__ Acomb_t) {
    __shared__ float s_red[256];
    __shared__ __align__(16) float s_aw[196];
    int b = blockIdx.x;
    int tid = threadIdx.x;
    int wid = tid >> 5, lane = tid & 31;
    const float* pb = g_ag_s + (size_t)b * 768;
    float v = -3.0e38f;
    if (tid < FF) {
        v = attn_b[tid];
#pragma unroll
        for (int z = 0; z < SPL; z++) v += pb[(size_t)z * BB * 768 + tid];
    }
    s_red[tid] = v;
    __syncthreads();
    for (int s = 128; s > 0; s >>= 1) {
        if (tid < s) s_red[tid] = fmaxf(s_red[tid], s_red[tid + s]);
        __syncthreads();
    }
    float mx = s_red[0];
    __syncthreads();
    float e = (tid < FF) ? expf(v - mx) : 0.f;
    s_red[tid] = e;
    __syncthreads();
    for (int s = 128; s > 0; s >>= 1) {
        if (tid < s) s_red[tid] += s_red[tid + s];
        __syncthreads();
    }
    float inv = 1.f / s_red[0];
    __syncthreads();
    if (tid < FF) s_aw[tid] = e * inv;
    __syncthreads();
    const float4* sa4 = (const float4*)s_aw;
    const float4* encb = (const float4*)(enc + (size_t)b * CC * FF);
    size_t cbase = (size_t)b * LKP;
    for (int grp = 0; grp < 8; grp++) {
#pragma unroll
        for (int ci = 0; ci < 8; ci++) {
            int c = wid * 64 + grp * 8 + ci;
            const float4* row = encb + (size_t)c * 49;
            float4 a0 = sa4[lane];
            float4 v0 = row[lane];
            float sum = v0.x * a0.x + v0.y * a0.y + v0.z * a0.z + v0.w * a0.w;
            if (lane < 17) {
                float4 a1 = sa4[lane + 32];
                float4 v1 = row[lane + 32];
                sum += v1.x * a1.x + v1.y * a1.y + v1.z * a1.z + v1.w * a1.w;
            }
#pragma unroll
            for (int o = 16; o > 0; o >>= 1) sum += __shfl_xor_sync(0xffffffffu, sum, o);
            if (lane == 0) {
                float gz = gate_b[c];
#pragma unroll
                for (int z = 0; z < SPL; z++) gz += pb[(size_t)z * BB * 768 + FF + c];
                float gamma = 1.f / (1.f + expf(-gz));
                float val = gamma * sum;
                __nv_bfloat16 hi, lo;
                split_bf16(val, hi, lo);
                Acomb_t[cbase + WVV + c] = hi;
                Acomb_t[cbase + KSEC + WVV + c] = hi;
                Acomb_t[cbase + 2 * KSEC + WVV + c] = lo;
            }
        }
    }
}

// P3: comb gemm, split-K x6, slice output. grid = 120
__global__ void __launch_bounds__(256)
k_p3(const __nv_bfloat16* __restrict__ A) {
    __shared__ __align__(16) char s_pipe[6 * 8192];
    float acc[4][4];
    int job = blockIdx.x;
    int z = job % SPL, tile = job / SPL;
    int bm = (tile / 5) * 64, bn = (tile % 5) * 64;
    tile_mma<NITS>(A, g_Wcomb2, bm, bn, z * KCH, s_pipe, acc);
    int tid = threadIdx.x, wid = tid >> 5, lane = tid & 31;
    float* dst = g_comb_s + (size_t)z * BB * 320;
    int r0 = bm + (wid & 3) * 16 + (lane >> 2);
    int c0 = bn + (wid >> 2) * 32 + 2 * (lane & 3);
#pragma unroll
    for (int q = 0; q < 4; q++)
#pragma unroll
        for (int h = 0; h < 2; h++) {
            dst[(r0 + 8 * h) * 320 + c0 + q * 8] = acc[q][2 * h];
            dst[(r0 + 8 * h) * 320 + c0 + q * 8 + 1] = acc[q][2 * h + 1];
        }
}

// P3b: reduce 6 comb slices + bias + relu -> g_Aih triple. grid = 302
__global__ void __launch_bounds__(256)
k_p3b(const float* __restrict__ comb_b) {
    int idx = blockIdx.x * 256 + threadIdx.x;
    if (idx >= BB * WVV) return;
    int b = idx / WVV, w = idx % WVV;
    float s = comb_b[w];
#pragma unroll
    for (int z = 0; z < SPL; z++) s += g_comb_s[((size_t)z * BB + b) * 320 + w];
    s = fmaxf(s, 0.f);
    __nv_bfloat16 hi, lo;
    split_bf16(s, hi, lo);
    size_t ib = (size_t)b * LKP + w;
    g_Aih[ib] = hi;
    g_Aih[ib + KSEC] = hi;
    g_Aih[ib + 2 * KSEC] = lo;
}

// P4: lstm gates gemm, split-K x6, slice output. grid = 768
__global__ void __launch_bounds__(256) k_p4() {
    __shared__ __align__(16) char s_pipe[6 * 8192];
    float acc[4][4];
    int job = blockIdx.x;
    int z = job % SPL, tile = job / SPL;
    int bm = (tile / 32) * 64, bn = (tile % 32) * 64;
    tile_mma<NITS>(g_Aih, g_Wl2, bm, bn, z * KCH, s_pipe, acc);
    int tid = threadIdx.x, wid = tid >> 5, lane = tid & 31;
    float* dst = g_gate_s + (size_t)z * BB * 2048;
    int r0 = bm + (wid & 3) * 16 + (lane >> 2);
    int c0 = bn + (wid >> 2) * 32 + 2 * (lane & 3);
#pragma unroll
    for (int q = 0; q < 4; q++)
#pragma unroll
        for (int h = 0; h < 2; h++) {
            dst[(r0 + 8 * h) * 2048 + c0 + q * 8] = acc[q][2 * h];
            dst[(r0 + 8 * h) * 2048 + c0 + q * 8 + 1] = acc[q][2 * h + 1];
        }
}

// P5: LSTM cell elementwise, sums 6 gate slices. grid = 512
__global__ void __launch_bounds__(256)
k_p5(int t, __nv_bfloat16* __restrict__ Aattn_next) {
    int idx = blockIdx.x * 256 + threadIdx.x;
    int b = idx >> 9, j = idx & 511;
    size_t gb = (size_t)b * 2048;
    float i_ = g_bl[j], f_ = g_bl[512 + j], g_ = g_bl[1024 + j], o_ = g_bl[1536 + j];
#pragma unroll
    for (int z = 0; z < SPL; z++) {
        const float* gr = g_gate_s + (size_t)z * BB * 2048 + gb;
        i_ += gr[j];
        f_ += gr[512 + j];
        g_ += gr[1024 + j];
        o_ += gr[1536 + j];
    }
    float si = 1.f / (1.f + expf(-i_));
    float sf = 1.f / (1.f + expf(-f_));
    float so = 1.f / (1.f + expf(-o_));
    float cn = sf * g_cst[idx] + si * tanhf(g_);
    float hn = so * tanhf(cn);
    g_cst[idx] = cn;
    __nv_bfloat16 hi, lo;
    split_bf16(hn, hi, lo);
    size_t ib = (size_t)b * LKP + WVV + j;
    g_Aih[ib] = hi;
    g_Aih[ib + KSEC] = hi;
    g_Aih[ib + 2 * KSEC] = lo;
    if (Aattn_next) {
        size_t ab = (size_t)b * LKP + WVV + j;
        Aattn_next[ab] = hi;
        Aattn_next[ab + KSEC] = hi;
        Aattn_next[ab + 2 * KSEC] = lo;
    }
    // vocab A row (single fp16 term)
    g_ap2[((size_t)t * BB + b) * KP2 + j] = __float2half(hn);
}

// ===================== vocab GEMM (fp16 single-term, one launch at end) =========
#define VBM 128
#define VBN 256
#define NKT2 (KP2 / 32)    // 16
#define STAGE_BYTES 24576
#define ASZ 8192
#define NSTAGE 3
#define VSMEM (NSTAGE * STAGE_BYTES)

__device__ __forceinline__ void issue_tile(const __half* __restrict__ Ag,
                                           const __half* __restrict__ Bg,
                                           uint32_t smb, int stage, int bm, int bn, int kt) {
    int tid = threadIdx.x;
    uint32_t abase = smb + stage * STAGE_BYTES;
    uint32_t bbase = abase + ASZ;
#pragma unroll
    for (int l = 0; l < 2; l++) {
        int idx = tid + 256 * l;
        int row = idx >> 2, c = idx & 3;
        cp16(abase + swz(row, c), Ag + (size_t)(bm + row) * KP2 + kt * 32 + c * 8);
    }
#pragma unroll
    for (int l = 0; l < 4; l++) {
        int idx = tid + 256 * l;
        int row = idx >> 2, c = idx & 3;
        cp16(bbase + swz(row, c), Bg + (size_t)(bn + row) * KP2 + kt * 32 + c * 8);
    }
    cp_commit();
}

__global__ void __launch_bounds__(256, 1)
gemm_vocab_mma(const __half* __restrict__ Ag, const __half* __restrict__ Bg,
               const float* __restrict__ bias, float* __restrict__ out) {
    extern __shared__ char sm[];
    uint32_t smb = smem_u32(sm);
    int tid = threadIdx.x;
    int wid = tid >> 5, lane = tid & 31;
    int wm = wid & 1, wn = wid >> 1;
    int bm = blockIdx.y * VBM, bn = blockIdx.x * VBN;

    int a_r = lane & 15;
    int a_c = lane >> 4;
    int b_r = (lane & 7) | (((lane >> 4) & 1) << 3);
    int b_c = (lane >> 3) & 1;

    float acc[4][8][4];
#pragma unroll
    for (int i = 0; i < 4; i++)
#pragma unroll
        for (int j = 0; j < 8; j++)
#pragma unroll
            for (int q = 0; q < 4; q++) acc[i][j][q] = 0.f;

    issue_tile(Ag, Bg, smb, 0, bm, bn, 0);
    issue_tile(Ag, Bg, smb, 1, bm, bn, 1);

    for (int kt = 0; kt < NKT2; kt++) {
        cp_wait<1>();
        __syncthreads();
        if (kt + 2 < NKT2) issue_tile(Ag, Bg, smb, (kt + 2) % NSTAGE, bm, bn, kt + 2);
        uint32_t abase = smb + (kt % NSTAGE) * STAGE_BYTES;
        uint32_t bbase = abase + ASZ;
#pragma unroll
        for (int s = 0; s < 2; s++) {
            uint32_t af[4][4], bf[4][4];
#pragma unroll
            for (int i = 0; i < 4; i++) {
                int row = wm * 64 + i * 16 + a_r;
                ldm_x4(af[i], abase + swz(row, s * 2 + a_c));
            }
#pragma unroll
            for (int jj = 0; jj < 4; jj++) {
                int row = wn * 64 + jj * 16 + b_r;
                ldm_x4(bf[jj], bbase + swz(row, s * 2 + b_c));
            }
#pragma unroll
            for (int i = 0; i < 4; i++)
#pragma unroll
                for (int jj = 0; jj < 4; jj++) {
                    mma_fp16(acc[i][2 * jj], af[i], bf[jj][0], bf[jj][1]);
                    mma_fp16(acc[i][2 * jj + 1], af[i], bf[jj][2], bf[jj][3]);
                }
        }
        __syncthreads();
    }

#pragma unroll
    for (int i = 0; i < 4; i++) {
#pragma unroll
        for (int j = 0; j < 8; j++) {
            int gm0 = bm + wm * 64 + i * 16 + (lane >> 2);
            int gn = bn + wn * 64 + j * 8 + 2 * (lane & 3);
#pragma unroll
            for (int h = 0; h < 2; h++) {
                int gm = gm0 + h * 8;
                int t = gm >> 8, b = gm & 255;
                float* row = out + ((size_t)b * TT + t) * VV;
                float c0 = acc[i][j][2 * h], c1 = acc[i][j][2 * h + 1];
                if (gn < VV) row[gn] = c0 + bias[gn];
                if (gn + 1 < VV) row[gn + 1] = c1 + bias[gn + 1];
            }
        }
    }
}

// ---------------- host launch (single stream, zero events) ----------------------
extern "C" void kernel_launch(void* const* d_in, const int* in_sizes, int n_in,
                              void* d_out, int out_size) {
    const float* enc     = (const float*)d_in[0];
    const float* wv      = (const float*)d_in[1];
    const float* attn_W  = (const float*)d_in[2];
    const float* attn_b  = (const float*)d_in[3];
    const float* comb_W  = (const float*)d_in[4];
    const float* comb_b  = (const float*)d_in[5];
    const float* gate_W  = (const float*)d_in[6];
    const float* gate_b  = (const float*)d_in[7];
    const float* Wih     = (const float*)d_in[8];
    const float* Whh     = (const float*)d_in[9];
    const float* bih     = (const float*)d_in[10];
    const float* bhh     = (const float*)d_in[11];
    const float* vocab_W = (const float*)d_in[12];
    const float* vocab_b = (const float*)d_in[13];
    float* out = (float*)d_out;

    __nv_bfloat16 *p_Aattn, *p_Acomb;
    __half *p_ap2, *p_wp2;
    cudaGetSymbolAddress((void**)&p_Aattn, g_Aattn);
    cudaGetSymbolAddress((void**)&p_Acomb, g_Acomb);
    cudaGetSymbolAddress((void**)&p_ap2, g_ap2);
    cudaGetSymbolAddress((void**)&p_wp2, g_wp2);

    cudaFuncSetAttribute(gemm_vocab_mma, cudaFuncAttributeMaxDynamicSharedMemorySize, VSMEM);

    zero_all_kernel<<<1024, 256>>>();
    setup_x2_kernel<<<(TT * BB * WVV + 255) / 256, 256>>>(wv);
    {
        long total = (long)NW0 + NW1 + NW2 + NW3;
        setup_weights_kernel<<<(unsigned)((total + 255) / 256), 256>>>(
            attn_W, gate_W, comb_W, Wih, Whh, bih, bhh, vocab_W);
    }

    for (int t = 0; t < TT; t++) {
        const __nv_bfloat16* Aat = p_Aattn + (size_t)t * BB * LKP;
        __nv_bfloat16* Aco = p_Acomb + (size_t)t * BB * LKP;
        k_p1<<<48 * SPL, 256>>>(Aat);
        k_p2<<<BB, 256>>>(enc, attn_b, gate_b, Aco);
        k_p3<<<20 * SPL, 256>>>(Aco);
        k_p3b<<<(BB * WVV + 255) / 256, 256>>>(comb_b);
        k_p4<<<128 * SPL, 256>>>();
        __nv_bfloat16* Anext = (t + 1 < TT) ? (p_Aattn + (size_t)(t + 1) * BB * LKP) : (__nv_bfloat16*)nullptr;
        k_p5<<<512, 256>>>(t, Anext);
    }
    // full vocab projection, one launch (fp16, M=5120)
    gemm_vocab_mma<<<dim3(NPAD / VBN, MROWS / VBM), 256, VSMEM>>>(p_ap2, p_wp2, vocab_b, out);
}

// round 15
// speedup vs baseline: 1.1532x; 1.0186x over previous
#include <cuda_runtime.h>
#include <cuda_bf16.h>
#include <cuda_fp16.h>
#include <cstdint>

#define BB 256
#define TT 20
#define HH 512
#define WVV 301
#define FF 196
#define CC 512
#define VV 9871
#define XK 813
#define NAG 708

#define KSEC 832          // padded K section (>=813, mult of 32)
#define LKP 2496          // 3 * KSEC
#define SPL 6             // split-K slices
#define KCH 416           // K per slice = LKP / SPL
#define NITS 13           // 416 / 32

#define KP2 512           // vocab K (single fp16 term)
#define NPAD 9984
#define MROWS (TT * BB)   // 5120

// ---------------- device globals ------------------------------------------------
__device__ __nv_bfloat16 g_Aattn[(size_t)TT * BB * LKP];  // [x|h] hi/hi/lo triple
__device__ __nv_bfloat16 g_Acomb[(size_t)TT * BB * LKP];  // [x|ctx]
__device__ __nv_bfloat16 g_Aih[(size_t)BB * LKP];         // [inp|h]
__device__ __nv_bfloat16 g_Wag2[(size_t)768 * LKP];       // [Whi|Wlo|Whi]
__device__ __nv_bfloat16 g_Wcomb2[(size_t)320 * LKP];
__device__ __nv_bfloat16 g_Wl2[(size_t)2048 * LKP];
__device__ float g_ag_s[SPL * BB * 768];     // attn+gate logit slices
__device__ float g_comb_s[SPL * BB * 320];   // comb raw slices
__device__ float g_gate_s[SPL * BB * 2048];  // lstm gate slices
__device__ float g_cst[BB * HH];             // cell state
__device__ float g_bl[2048];                 // bih + bhh
__device__ __half g_ap2[(size_t)MROWS * KP2];  // vocab A (fp16 h)
__device__ __half g_wp2[(size_t)NPAD * KP2];   // vocab W (fp16)

// ---------------- common helpers ------------------------------------------------
__device__ __forceinline__ uint32_t smem_u32(const void* p) {
    uint32_t a;
    asm("{ .reg .u64 t; cvta.to.shared.u64 t, %1; cvt.u32.u64 %0, t; }" : "=r"(a) : "l"(p));
    return a;
}
__device__ __forceinline__ void cp16(uint32_t saddr, const void* gptr) {
    asm volatile("cp.async.cg.shared.global [%0], [%1], 16;" :: "r"(saddr), "l"(gptr));
}
__device__ __forceinline__ void cp_commit() { asm volatile("cp.async.commit_group;"); }
template <int N>
__device__ __forceinline__ void cp_wait() { asm volatile("cp.async.wait_group %0;" :: "n"(N)); }
__device__ __forceinline__ void ldm_x4(uint32_t* r, uint32_t addr) {
    asm volatile("ldmatrix.sync.aligned.m8n8.x4.shared.b16 {%0,%1,%2,%3}, [%4];"
                 : "=r"(r[0]), "=r"(r[1]), "=r"(r[2]), "=r"(r[3]) : "r"(addr));
}
__device__ __forceinline__ void mma_bf16(float* c, const uint32_t* a, uint32_t b0, uint32_t b1) {
    asm volatile(
        "mma.sync.aligned.m16n8k16.row.col.f32.bf16.bf16.f32 "
        "{%0,%1,%2,%3}, {%4,%5,%6,%7}, {%8,%9}, {%0,%1,%2,%3};"
        : "+f"(c[0]), "+f"(c[1]), "+f"(c[2]), "+f"(c[3])
        : "r"(a[0]), "r"(a[1]), "r"(a[2]), "r"(a[3]), "r"(b0), "r"(b1));
}
__device__ __forceinline__ void mma_fp16(float* c, const uint32_t* a, uint32_t b0, uint32_t b1) {
    asm volatile(
        "mma.sync.aligned.m16n8k16.row.col.f32.f16.f16.f32 "
        "{%0,%1,%2,%3}, {%4,%5,%6,%7}, {%8,%9}, {%0,%1,%2,%3};"
        : "+f"(c[0]), "+f"(c[1]), "+f"(c[2]), "+f"(c[3])
        : "r"(a[0]), "r"(a[1]), "r"(a[2]), "r"(a[3]), "r"(b0), "r"(b1));
}
// 64B-row swizzle for BK=32 tiles
__device__ __forceinline__ uint32_t swz(int row, int c) {
    return (uint32_t)(row * 64 + ((c ^ ((row >> 1) & 3)) * 16));
}
__device__ __forceinline__ void split_bf16(float v, __nv_bfloat16& hi, __nv_bfloat16& lo) {
    hi = __float2bfloat16(v);
    lo = __float2bfloat16(v - __bfloat162float(hi));
}

// ---- 64x64 tile bf16 GEMM, 6-stage pipeline, SINGLE sync per iteration --------
template <int NIT>
__device__ __forceinline__ void tile_mma(const __nv_bfloat16* __restrict__ Ag,
                                         const __nv_bfloat16* __restrict__ Bg,
                                         int bm, int bn, int koff, char* spipe,
                                         float acc[4][4]) {
    uint32_t smb = smem_u32(spipe);
    int tid = threadIdx.x;
    int wid = tid >> 5, lane = tid & 31;
    int wm = wid & 3, wn = wid >> 2;
    int a_r = lane & 15, a_c = lane >> 4;
    int b_r = (lane & 7) | (((lane >> 4) & 1) << 3);
    int b_c = (lane >> 3) & 1;
    int lrow = tid >> 2, lc = tid & 3;
#pragma unroll
    for (int q = 0; q < 4; q++)
#pragma unroll
        for (int j = 0; j < 4; j++) acc[q][j] = 0.f;

    const __nv_bfloat16* Abase = Ag + (size_t)(bm + lrow) * LKP + koff + lc * 8;
    const __nv_bfloat16* Bbase = Bg + (size_t)(bn + lrow) * LKP + koff + lc * 8;

#pragma unroll
    for (int st = 0; st < 5; st++) {
        if (st < NIT) {
            uint32_t ab = smb + st * 8192;
            cp16(ab + swz(lrow, lc), Abase + st * 32);
            cp16(ab + 4096 + swz(lrow, lc), Bbase + st * 32);
        }
        cp_commit();
    }
    for (int kt = 0; kt < NIT; kt++) {
        cp_wait<4>();
        __syncthreads();
        int nx = kt + 5;
        if (nx < NIT) {
            uint32_t ab = smb + (nx % 6) * 8192;
            cp16(ab + swz(lrow, lc), Abase + (size_t)nx * 32);
            cp16(ab + 4096 + swz(lrow, lc), Bbase + (size_t)nx * 32);
        }
        cp_commit();
        uint32_t ab = smb + (kt % 6) * 8192;
        uint32_t bb = ab + 4096;
#pragma unroll
        for (int s = 0; s < 2; s++) {
            uint32_t af[4];
            ldm_x4(af, ab + swz(wm * 16 + a_r, s * 2 + a_c));
#pragma unroll
            for (int jj = 0; jj < 2; jj++) {
                uint32_t bf[4];
                ldm_x4(bf, bb + swz(wn * 32 + jj * 16 + b_r, s * 2 + b_c));
                mma_bf16(acc[2 * jj], af, bf[0], bf[1]);
                mma_bf16(acc[2 * jj + 1], af, bf[2], bf[3]);
            }
        }
        // no trailing sync: next iteration's top barrier protects slot reuse
    }
}

// ---- WIDE 64x128 tile bf16 GEMM, 5-stage (12KB/stage) pipeline, single sync ---
#define WSTG 12288
#define WSMEM (5 * WSTG)   // 61440
template <int NIT>
__device__ __forceinline__ void tile_mma_w(const __nv_bfloat16* __restrict__ Ag,
                                           const __nv_bfloat16* __restrict__ Bg,
                                           int bm, int bn, int koff, char* spipe,
                                           float acc[8][4]) {
    uint32_t smb = smem_u32(spipe);
    int tid = threadIdx.x;
    int wid = tid >> 5, lane = tid & 31;
    int wm = wid & 3, wn = wid >> 2;     // 4 m-groups of 16, 2 n-groups of 64
    int a_r = lane & 15, a_c = lane >> 4;
    int b_r = (lane & 7) | (((lane >> 4) & 1) << 3);
    int b_c = (lane >> 3) & 1;
#pragma unroll
    for (int q = 0; q < 8; q++)
#pragma unroll
        for (int j = 0; j < 4; j++) acc[q][j] = 0.f;

    // loaders: A 256 chunks (64r x 4c), B 512 chunks (128r x 4c); 3 chunks/thread
    int arow = tid >> 2, ac = tid & 3;
    const __nv_bfloat16* Abase = Ag + (size_t)(bm + arow) * LKP + koff + ac * 8;
    const __nv_bfloat16* B0 = Bg + (size_t)(bn + arow) * LKP + koff + ac * 8;          // B rows 0..63
    const __nv_bfloat16* B1 = Bg + (size_t)(bn + 64 + arow) * LKP + koff + ac * 8;     // B rows 64..127
    uint32_t aoff = swz(arow, ac);
    uint32_t boff0 = 4096 + swz(arow, ac);
    uint32_t boff1 = 4096 + swz(64 + arow, ac);

#pragma unroll
    for (int st = 0; st < 4; st++) {
        if (st < NIT) {
            uint32_t base = smb + st * WSTG;
            cp16(base + aoff, Abase + st * 32);
            cp16(base + boff0, B0 + st * 32);
            cp16(base + boff1, B1 + st * 32);
        }
        cp_commit();
    }
    for (int kt = 0; kt < NIT; kt++) {
        cp_wait<3>();
        __syncthreads();
        int nx = kt + 4;
        if (nx < NIT) {
            uint32_t base = smb + (nx % 5) * WSTG;
            cp16(base + aoff, Abase + (size_t)nx * 32);
            cp16(base + boff0, B0 + (size_t)nx * 32);
            cp16(base + boff1, B1 + (size_t)nx * 32);
        }
        cp_commit();
        uint32_t ab = smb + (kt % 5) * WSTG;
        uint32_t bb = ab + 4096;
#pragma unroll
        for (int s = 0; s < 2; s++) {
            uint32_t af[4];
            ldm_x4(af, ab + swz(wm * 16 + a_r, s * 2 + a_c));
#pragma unroll
            for (int jj = 0; jj < 4; jj++) {
                uint32_t bf[4];
                ldm_x4(bf, bb + swz(wn * 64 + jj * 16 + b_r, s * 2 + b_c));
                mma_bf16(acc[2 * jj], af, bf[0], bf[1]);
                mma_bf16(acc[2 * jj + 1], af, bf[2], bf[3]);
            }
        }
    }
}

// ---------------- setup kernels (3 launches before loop) ------------------------
__global__ void zero_all_kernel() {
    size_t stride = (size_t)gridDim.x * blockDim.x;
    size_t id = (size_t)blockIdx.x * blockDim.x + threadIdx.x;
    uint4 z = make_uint4(0, 0, 0, 0);
    uint4* pa = (uint4*)g_Aattn;
    size_t nA = sizeof(g_Aattn) / 16;
    for (size_t i = id; i < nA; i += stride) pa[i] = z;
    uint4* pc = (uint4*)g_Acomb;
    for (size_t i = id; i < nA; i += stride) pc[i] = z;
    uint4* pi = (uint4*)g_Aih;
    size_t nI = sizeof(g_Aih) / 16;
    for (size_t i = id; i < nI; i += stride) pi[i] = z;
    uint4* ps = (uint4*)g_cst;
    size_t nS = sizeof(g_cst) / 16;
    for (size_t i = id; i < nS; i += stride) ps[i] = z;
}

__global__ void setup_x2_kernel(const float* __restrict__ wv) {
    int idx = blockIdx.x * blockDim.x + threadIdx.x;
    const int total = TT * BB * WVV;
    if (idx >= total) return;
    int t = idx / (BB * WVV);
    int r = idx % (BB * WVV);
    int b = r / WVV, w = r % WVV;
    float v = (t == 0) ? 0.f : wv[(size_t)b * TT * WVV + (size_t)(t - 1) * WVV + w];
    __nv_bfloat16 hi, lo;
    split_bf16(v, hi, lo);
    size_t base = ((size_t)t * BB + b) * LKP;
    g_Aattn[base + w] = hi;
    g_Aattn[base + KSEC + w] = hi;
    g_Aattn[base + 2 * KSEC + w] = lo;
    g_Acomb[base + w] = hi;
    g_Acomb[base + KSEC + w] = hi;
    g_Acomb[base + 2 * KSEC + w] = lo;
}

#define NW0 (768 * KSEC)
#define NW1 (320 * KSEC)
#define NW2 (2048 * KSEC)
#define NW3 (NPAD * HH)
__global__ void setup_weights_kernel(const float* __restrict__ attn_W,
                                     const float* __restrict__ gate_W,
                                     const float* __restrict__ comb_W,
                                     const float* __restrict__ Wih,
                                     const float* __restrict__ Whh,
                                     const float* __restrict__ bih,
                                     const float* __restrict__ bhh,
                                     const float* __restrict__ vw) {
    long idx = (long)blockIdx.x * blockDim.x + threadIdx.x;
    if (idx < 2048) g_bl[idx] = bih[idx] + bhh[idx];
    if (idx < NW0) {
        int n = idx / KSEC, k = idx % KSEC;
        float v = 0.f;
        if (k < XK) {
            if (n < FF) v = attn_W[(size_t)n * XK + k];
            else if (n < NAG && k >= WVV) v = gate_W[(size_t)(n - FF) * HH + (k - WVV)];
        }
        __nv_bfloat16 hi, lo;
        split_bf16(v, hi, lo);
        size_t base = (size_t)n * LKP;
        g_Wag2[base + k] = hi;
        g_Wag2[base + KSEC + k] = lo;
        g_Wag2[base + 2 * KSEC + k] = hi;
        return;
    }
    idx -= NW0;
    if (idx < NW1) {
        int n = idx / KSEC, k = idx % KSEC;
        float v = (n < WVV && k < XK) ? comb_W[(size_t)n * XK + k] : 0.f;
        __nv_bfloat16 hi, lo;
        split_bf16(v, hi, lo);
        size_t base = (size_t)n * LKP;
        g_Wcomb2[base + k] = hi;
        g_Wcomb2[base + KSEC + k] = lo;
        g_Wcomb2[base + 2 * KSEC + k] = hi;
        return;
    }
    idx -= NW1;
    if (idx < NW2) {
        int n = idx / KSEC, k = idx % KSEC;
        float v = 0.f;
        if (k < XK) v = (k < WVV) ? Wih[(size_t)n * WVV + k] : Whh[(size_t)n * HH + (k - WVV)];
        __nv_bfloat16 hi, lo;
        split_bf16(v, hi, lo);
        size_t base = (size_t)n * LKP;
        g_Wl2[base + k] = hi;
        g_Wl2[base + KSEC + k] = lo;
        g_Wl2[base + 2 * KSEC + k] = hi;
        return;
    }
    idx -= NW2;
    if (idx < NW3) {
        int n = idx / HH, k = idx % HH;
        float v = (n < VV) ? vw[(size_t)n * HH + k] : 0.f;
        g_wp2[(size_t)n * KP2 + k] = __float2half(v);
    }
}

// ---------------- loop kernels ---------------------------------------------------
// P1: attn+gate logits, WIDE tiles, split-K x6. grid = 4m x 6n x 6z = 144
__global__ void __launch_bounds__(256) k_p1(const __nv_bfloat16* __restrict__ A) {
    extern __shared__ __align__(16) char s_dyn[];
    float acc[8][4];
    int job = blockIdx.x;
    int z = job % SPL, tile = job / SPL;
    int bm = (tile / 6) * 64, bn = (tile % 6) * 128;
    tile_mma_w<NITS>(A, g_Wag2, bm, bn, z * KCH, s_dyn, acc);
    int tid = threadIdx.x, wid = tid >> 5, lane = tid & 31;
    float* dst = g_ag_s + (size_t)z * BB * 768;
    int r0 = bm + (wid & 3) * 16 + (lane >> 2);
    int c0 = bn + (wid >> 2) * 64 + 2 * (lane & 3);
#pragma unroll
    for (int q = 0; q < 8; q++)
#pragma unroll
        for (int h = 0; h < 2; h++) {
            dst[(r0 + 8 * h) * 768 + c0 + q * 8] = acc[q][2 * h];
            dst[(r0 + 8 * h) * 768 + c0 + q * 8 + 1] = acc[q][2 * h + 1];
        }
}

// P2: softmax + gated ctx (sums 6 slices). grid = BB
__global__ void __launch_bounds__(256)
k_p2(const float* __restrict__ enc, const float* __restrict__ attn_b,
     const float* __restrict__ gate_b, __nv_bfloat16* __restrict__ Acomb_t) {
    __shared__ float s_red[256];
    __shared__ __align__(16) float s_aw[196];
    int b = blockIdx.x;
    int tid = threadIdx.x;
    int wid = tid >> 5, lane = tid & 31;
    const float* pb = g_ag_s + (size_t)b * 768;
    float v = -3.0e38f;
    if (tid < FF) {
        v = attn_b[tid];
#pragma unroll
        for (int z = 0; z < SPL; z++) v += pb[(size_t)z * BB * 768 + tid];
    }
    s_red[tid] = v;
    __syncthreads();
    for (int s = 128; s > 0; s >>= 1) {
        if (tid < s) s_red[tid] = fmaxf(s_red[tid], s_red[tid + s]);
        __syncthreads();
    }
    float mx = s_red[0];
    __syncthreads();
    float e = (tid < FF) ? expf(v - mx) : 0.f;
    s_red[tid] = e;
    __syncthreads();
    for (int s = 128; s > 0; s >>= 1) {
        if (tid < s) s_red[tid] += s_red[tid + s];
        __syncthreads();
    }
    float inv = 1.f / s_red[0];
    __syncthreads();
    if (tid < FF) s_aw[tid] = e * inv;
    __syncthreads();
    const float4* sa4 = (const float4*)s_aw;
    const float4* encb = (const float4*)(enc + (size_t)b * CC * FF);
    size_t cbase = (size_t)b * LKP;
    for (int grp = 0; grp < 8; grp++) {
#pragma unroll
        for (int ci = 0; ci < 8; ci++) {
            int c = wid * 64 + grp * 8 + ci;
            const float4* row = encb + (size_t)c * 49;
            float4 a0 = sa4[lane];
            float4 v0 = row[lane];
            float sum = v0.x * a0.x + v0.y * a0.y + v0.z * a0.z + v0.w * a0.w;
            if (lane < 17) {
                float4 a1 = sa4[lane + 32];
                float4 v1 = row[lane + 32];
                sum += v1.x * a1.x + v1.y * a1.y + v1.z * a1.z + v1.w * a1.w;
            }
#pragma unroll
            for (int o = 16; o > 0; o >>= 1) sum += __shfl_xor_sync(0xffffffffu, sum, o);
            if (lane == 0) {
                float gz = gate_b[c];
#pragma unroll
                for (int z = 0; z < SPL; z++) gz += pb[(size_t)z * BB * 768 + FF + c];
                float gamma = 1.f / (1.f + expf(-gz));
                float val = gamma * sum;
                __nv_bfloat16 hi, lo;
                split_bf16(val, hi, lo);
                Acomb_t[cbase + WVV + c] = hi;
                Acomb_t[cbase + KSEC + WVV + c] = hi;
                Acomb_t[cbase + 2 * KSEC + WVV + c] = lo;
            }
        }
    }
}

// P3: comb gemm, split-K x6, slice output. grid = 120 (narrow tiles, N=320)
__global__ void __launch_bounds__(256)
k_p3(const __nv_bfloat16* __restrict__ A) {
    __shared__ __align__(16) char s_pipe[6 * 8192];
    float acc[4][4];
    int job = blockIdx.x;
    int z = job % SPL, tile = job / SPL;
    int bm = (tile / 5) * 64, bn = (tile % 5) * 64;
    tile_mma<NITS>(A, g_Wcomb2, bm, bn, z * KCH, s_pipe, acc);
    int tid = threadIdx.x, wid = tid >> 5, lane = tid & 31;
    float* dst = g_comb_s + (size_t)z * BB * 320;
    int r0 = bm + (wid & 3) * 16 + (lane >> 2);
    int c0 = bn + (wid >> 2) * 32 + 2 * (lane & 3);
#pragma unroll
    for (int q = 0; q < 4; q++)
#pragma unroll
        for (int h = 0; h < 2; h++) {
            dst[(r0 + 8 * h) * 320 + c0 + q * 8] = acc[q][2 * h];
            dst[(r0 + 8 * h) * 320 + c0 + q * 8 + 1] = acc[q][2 * h + 1];
        }
}

// P3b: reduce 6 comb slices + bias + relu -> g_Aih triple. grid = 302
__global__ void __launch_bounds__(256)
k_p3b(const float* __restrict__ comb_b) {
    int idx = blockIdx.x * 256 + threadIdx.x;
    if (idx >= BB * WVV) return;
    int b = idx / WVV, w = idx % WVV;
    float s = comb_b[w];
#pragma unroll
    for (int z = 0; z < SPL; z++) s += g_comb_s[((size_t)z * BB + b) * 320 + w];
    s = fmaxf(s, 0.f);
    __nv_bfloat16 hi, lo;
    split_bf16(s, hi, lo);
    size_t ib = (size_t)b * LKP + w;
    g_Aih[ib] = hi;
    g_Aih[ib + KSEC] = hi;
    g_Aih[ib + 2 * KSEC] = lo;
}

// P4: lstm gates gemm, WIDE tiles, split-K x6. grid = 4m x 16n x 6z = 384
__global__ void __launch_bounds__(256) k_p4() {
    extern __shared__ __align__(16) char s_dyn[];
    float acc[8][4];
    int job = blockIdx.x;
    int z = job % SPL, tile = job / SPL;
    int bm = (tile / 16) * 64, bn = (tile % 16) * 128;
    tile_mma_w<NITS>(g_Aih, g_Wl2, bm, bn, z * KCH, s_dyn, acc);
    int tid = threadIdx.x, wid = tid >> 5, lane = tid & 31;
    float* dst = g_gate_s + (size_t)z * BB * 2048;
    int r0 = bm + (wid & 3) * 16 + (lane >> 2);
    int c0 = bn + (wid >> 2) * 64 + 2 * (lane & 3);
#pragma unroll
    for (int q = 0; q < 8; q++)
#pragma unroll
        for (int h = 0; h < 2; h++) {
            dst[(r0 + 8 * h) * 2048 + c0 + q * 8] = acc[q][2 * h];
            dst[(r0 + 8 * h) * 2048 + c0 + q * 8 + 1] = acc[q][2 * h + 1];
        }
}

// P5: LSTM cell elementwise, sums 6 gate slices. grid = 512
__global__ void __launch_bounds__(256)
k_p5(int t, __nv_bfloat16* __restrict__ Aattn_next) {
    int idx = blockIdx.x * 256 + threadIdx.x;
    int b = idx >> 9, j = idx & 511;
    size_t gb = (size_t)b * 2048;
    float i_ = g_bl[j], f_ = g_bl[512 + j], g_ = g_bl[1024 + j], o_ = g_bl[1536 + j];
#pragma unroll
    for (int z = 0; z < SPL; z++) {
        const float* gr = g_gate_s + (size_t)z * BB * 2048 + gb;
        i_ += gr[j];
        f_ += gr[512 + j];
        g_ += gr[1024 + j];
        o_ += gr[1536 + j];
    }
    float si = 1.f / (1.f + expf(-i_));
    float sf = 1.f / (1.f + expf(-f_));
    float so = 1.f / (1.f + expf(-o_));
    float cn = sf * g_cst[idx] + si * tanhf(g_);
    float hn = so * tanhf(cn);
    g_cst[idx] = cn;
    __nv_bfloat16 hi, lo;
    split_bf16(hn, hi, lo);
    size_t ib = (size_t)b * LKP + WVV + j;
    g_Aih[ib] = hi;
    g_Aih[ib + KSEC] = hi;
    g_Aih[ib + 2 * KSEC] = lo;
    if (Aattn_next) {
        size_t ab = (size_t)b * LKP + WVV + j;
        Aattn_next[ab] = hi;
        Aattn_next[ab + KSEC] = hi;
        Aattn_next[ab + 2 * KSEC] = lo;
    }
    g_ap2[((size_t)t * BB + b) * KP2 + j] = __float2half(hn);
}

// ===================== vocab GEMM (fp16, one launch at end) =====================
#define VBM 128
#define VBN 256
#define NKT2 (KP2 / 32)    // 16
#define STAGE_BYTES 24576
#define ASZ 8192
#define NSTAGE 3
#define VSMEM (NSTAGE * STAGE_BYTES)

__device__ __forceinline__ void issue_tile(const __half* __restrict__ Ag,
                                           const __half* __restrict__ Bg,
                                           uint32_t smb, int stage, int bm, int bn, int kt) {
    int tid = threadIdx.x;
    uint32_t abase = smb + stage * STAGE_BYTES;
    uint32_t bbase = abase + ASZ;
#pragma unroll
    for (int l = 0; l < 2; l++) {
        int idx = tid + 256 * l;
        int row = idx >> 2, c = idx & 3;
        cp16(abase + swz(row, c), Ag + (size_t)(bm + row) * KP2 + kt * 32 + c * 8);
    }
#pragma unroll
    for (int l = 0; l < 4; l++) {
        int idx = tid + 256 * l;
        int row = idx >> 2, c = idx & 3;
        cp16(bbase + swz(row, c), Bg + (size_t)(bn + row) * KP2 + kt * 32 + c * 8);
    }
    cp_commit();
}

__global__ void __launch_bounds__(256, 1)
gemm_vocab_mma(const __half* __restrict__ Ag, const __half* __restrict__ Bg,
               const float* __restrict__ bias, float* __restrict__ out) {
    extern __shared__ char sm[];
    uint32_t smb = smem_u32(sm);
    int tid = threadIdx.x;
    int wid = tid >> 5, lane = tid & 31;
    int wm = wid & 1, wn = wid >> 1;
    int bm = blockIdx.y * VBM, bn = blockIdx.x * VBN;

    int a_r = lane & 15;
    int a_c = lane >> 4;
    int b_r = (lane & 7) | (((lane >> 4) & 1) << 3);
    int b_c = (lane >> 3) & 1;

    float acc[4][8][4];
#pragma unroll
    for (int i = 0; i < 4; i++)
#pragma unroll
        for (int j = 0; j < 8; j++)
#pragma unroll
            for (int q = 0; q < 4; q++) acc[i][j][q] = 0.f;

    issue_tile(Ag, Bg, smb, 0, bm, bn, 0);
    issue_tile(Ag, Bg, smb, 1, bm, bn, 1);

    for (int kt = 0; kt < NKT2; kt++) {
        cp_wait<1>();
        __syncthreads();
        if (kt + 2 < NKT2) issue_tile(Ag, Bg, smb, (kt + 2) % NSTAGE, bm, bn, kt + 2);
        uint32_t abase = smb + (kt % NSTAGE) * STAGE_BYTES;
        uint32_t bbase = abase + ASZ;
#pragma unroll
        for (int s = 0; s < 2; s++) {
            uint32_t af[4][4], bf[4][4];
#pragma unroll
            for (int i = 0; i < 4; i++) {
                int row = wm * 64 + i * 16 + a_r;
                ldm_x4(af[i], abase + swz(row, s * 2 + a_c));
            }
#pragma unroll
            for (int jj = 0; jj < 4; jj++) {
                int row = wn * 64 + jj * 16 + b_r;
                ldm_x4(bf[jj], bbase + swz(row, s * 2 + b_c));
            }
#pragma unroll
            for (int i = 0; i < 4; i++)
#pragma unroll
                for (int jj = 0; jj < 4; jj++) {
                    mma_fp16(acc[i][2 * jj], af[i], bf[jj][0], bf[jj][1]);
                    mma_fp16(acc[i][2 * jj + 1], af[i], bf[jj][2], bf[jj][3]);
                }
        }
        // no trailing sync (top barrier of next iter protects slot reuse)
    }

#pragma unroll
    for (int i = 0; i < 4; i++) {
#pragma unroll
        for (int j = 0; j < 8; j++) {
            int gm0 = bm + wm * 64 + i * 16 + (lane >> 2);
            int gn = bn + wn * 64 + j * 8 + 2 * (lane & 3);
#pragma unroll
            for (int h = 0; h < 2; h++) {
                int gm = gm0 + h * 8;
                int t = gm >> 8, b = gm & 255;
                float* row = out + ((size_t)b * TT + t) * VV;
                float c0 = acc[i][j][2 * h], c1 = acc[i][j][2 * h + 1];
                if (gn < VV) row[gn] = c0 + bias[gn];
                if (gn + 1 < VV) row[gn + 1] = c1 + bias[gn + 1];
            }
        }
    }
}

// ---------------- host launch (single stream, zero events) ----------------------
extern "C" void kernel_launch(void* const* d_in, const int* in_sizes, int n_in,
                              void* d_out, int out_size) {
    const float* enc     = (const float*)d_in[0];
    const float* wv      = (const float*)d_in[1];
    const float* attn_W  = (const float*)d_in[2];
    const float* attn_b  = (const float*)d_in[3];
    const float* comb_W  = (const float*)d_in[4];
    const float* comb_b  = (const float*)d_in[5];
    const float* gate_W  = (const float*)d_in[6];
    const float* gate_b  = (const float*)d_in[7];
    const float* Wih     = (const float*)d_in[8];
    const float* Whh     = (const float*)d_in[9];
    const float* bih     = (const float*)d_in[10];
    const float* bhh     = (const float*)d_in[11];
    const float* vocab_W = (const float*)d_in[12];
    const float* vocab_b = (const float*)d_in[13];
    float* out = (float*)d_out;

    __nv_bfloat16 *p_Aattn, *p_Acomb;
    __half *p_ap2, *p_wp2;
    cudaGetSymbolAddress((void**)&p_Aattn, g_Aattn);
    cudaGetSymbolAddress((void**)&p_Acomb, g_Acomb);
    cudaGetSymbolAddress((void**)&p_ap2, g_ap2);
    cudaGetSymbolAddress((void**)&p_wp2, g_wp2);

    cudaFuncSetAttribute(gemm_vocab_mma, cudaFuncAttributeMaxDynamicSharedMemorySize, VSMEM);
    cudaFuncSetAttribute(k_p1, cudaFuncAttributeMaxDynamicSharedMemorySize, WSMEM);
    cudaFuncSetAttribute(k_p4, cudaFuncAttributeMaxDynamicSharedMemorySize, WSMEM);

    zero_all_kernel<<<1024, 256>>>();
    setup_x2_kernel<<<(TT * BB * WVV + 255) / 256, 256>>>(wv);
    {
        long total = (long)NW0 + NW1 + NW2 + NW3;
        setup_weights_kernel<<<(unsigned)((total + 255) / 256), 256>>>(
            attn_W, gate_W, comb_W, Wih, Whh, bih, bhh, vocab_W);
    }

    for (int t = 0; t < TT; t++) {
        const __nv_bfloat16* Aat = p_Aattn + (size_t)t * BB * LKP;
        __nv_bfloat16* Aco = p_Acomb + (size_t)t * BB * LKP;
        k_p1<<<24 * SPL, 256, WSMEM>>>(Aat);
        k_p2<<<BB, 256>>>(enc, attn_b, gate_b, Aco);
        k_p3<<<20 * SPL, 256>>>(Aco);
        k_p3b<<<(BB * WVV + 255) / 256, 256>>>(comb_b);
        k_p4<<<64 * SPL, 256, WSMEM>>>();
        __nv_bfloat16* Anext = (t + 1 < TT) ? (p_Aattn + (size_t)(t + 1) * BB * LKP) : (__nv_bfloat16*)nullptr;
        k_p5<<<512, 256>>>(t, Anext);
    }
    gemm_vocab_mma<<<dim3(NPAD / VBN, MROWS / VBM), 256, VSMEM>>>(p_ap2, p_wp2, vocab_b, out);
}

// round 16
// speedup vs baseline: 1.4192x; 1.2307x over previous
#include <cuda_runtime.h>
#include <cuda_bf16.h>
#include <cuda_fp16.h>
#include <cstdint>

#define BB 256
#define TT 20
#define HH 512
#define WVV 301
#define FF 196
#define CC 512
#define VV 9871
#define XK 813
#define NAG 708

#define KSEC 832          // padded K section (>=813, mult of 32)
#define LKP 1664          // 2 * KSEC (fp16 hi|lo)
#define NSEC 26           // 832 / 32 iters per section

#define KP2 512           // vocab K (single fp16 term)
#define NPAD 9984
#define MROWS (TT * BB)   // 5120

// ---------------- device globals ------------------------------------------------
__device__ __half g_Aattn[(size_t)TT * BB * LKP];  // [x|h] hi|lo
__device__ __half g_Acomb[(size_t)TT * BB * LKP];  // [x|ctx] hi|lo
__device__ __half g_Aih[(size_t)BB * LKP];         // [inp|h] hi|lo
__device__ __half g_Wag2[(size_t)768 * LKP];       // [Whi|Wlo]
__device__ __half g_Wcomb2[(size_t)320 * LKP];
__device__ __half g_Wl2[(size_t)2048 * LKP];
__device__ __half g_enc2[(size_t)BB * CC * FF];    // fp16 encoding copy
__device__ float g_ag_s[2 * BB * 768];     // attn+gate logit slices (split-2)
__device__ float g_gate_s[2 * BB * 2048];  // lstm gate slices (split-2)
__device__ float g_cst[BB * HH];           // cell state
__device__ float g_bl[2048];               // bih + bhh
__device__ __half g_ap2[(size_t)MROWS * KP2];  // vocab A (fp16 h)
__device__ __half g_wp2[(size_t)NPAD * KP2];   // vocab W (fp16)

// ---------------- common helpers ------------------------------------------------
__device__ __forceinline__ uint32_t smem_u32(const void* p) {
    uint32_t a;
    asm("{ .reg .u64 t; cvta.to.shared.u64 t, %1; cvt.u32.u64 %0, t; }" : "=r"(a) : "l"(p));
    return a;
}
__device__ __forceinline__ void cp16(uint32_t saddr, const void* gptr) {
    asm volatile("cp.async.cg.shared.global [%0], [%1], 16;" :: "r"(saddr), "l"(gptr));
}
__device__ __forceinline__ void cp_commit() { asm volatile("cp.async.commit_group;"); }
template <int N>
__device__ __forceinline__ void cp_wait() { asm volatile("cp.async.wait_group %0;" :: "n"(N)); }
__device__ __forceinline__ void ldm_x4(uint32_t* r, uint32_t addr) {
    asm volatile("ldmatrix.sync.aligned.m8n8.x4.shared.b16 {%0,%1,%2,%3}, [%4];"
                 : "=r"(r[0]), "=r"(r[1]), "=r"(r[2]), "=r"(r[3]) : "r"(addr));
}
__device__ __forceinline__ void mma_fp16(float* c, const uint32_t* a, uint32_t b0, uint32_t b1) {
    asm volatile(
        "mma.sync.aligned.m16n8k16.row.col.f32.f16.f16.f32 "
        "{%0,%1,%2,%3}, {%4,%5,%6,%7}, {%8,%9}, {%0,%1,%2,%3};"
        : "+f"(c[0]), "+f"(c[1]), "+f"(c[2]), "+f"(c[3])
        : "r"(a[0]), "r"(a[1]), "r"(a[2]), "r"(a[3]), "r"(b0), "r"(b1));
}
// 64B-row swizzle for BK=32 tiles
__device__ __forceinline__ uint32_t swz(int row, int c) {
    return (uint32_t)(row * 64 + ((c ^ ((row >> 1) & 3)) * 16));
}
__device__ __forceinline__ void split_fp16(float v, __half& hi, __half& lo) {
    hi = __float2half(v);
    lo = __float2half(v - __half2float(hi));
}

// ---- 64x64 tile fp16 GEMM, 6-stage pipeline, single sync per iteration --------
template <int NIT>
__device__ __forceinline__ void tile_mma(const __half* __restrict__ Ag,
                                         const __half* __restrict__ Bg,
                                         int bm, int bn, int koff, char* spipe,
                                         float acc[4][4]) {
    uint32_t smb = smem_u32(spipe);
    int tid = threadIdx.x;
    int wid = tid >> 5, lane = tid & 31;
    int wm = wid & 3, wn = wid >> 2;
    int a_r = lane & 15, a_c = lane >> 4;
    int b_r = (lane & 7) | (((lane >> 4) & 1) << 3);
    int b_c = (lane >> 3) & 1;
    int lrow = tid >> 2, lc = tid & 3;
#pragma unroll
    for (int q = 0; q < 4; q++)
#pragma unroll
        for (int j = 0; j < 4; j++) acc[q][j] = 0.f;

    const __half* Abase = Ag + (size_t)(bm + lrow) * LKP + koff + lc * 8;
    const __half* Bbase = Bg + (size_t)(bn + lrow) * LKP + koff + lc * 8;

#pragma unroll
    for (int st = 0; st < 5; st++) {
        if (st < NIT) {
            uint32_t ab = smb + st * 8192;
            cp16(ab + swz(lrow, lc), Abase + st * 32);
            cp16(ab + 4096 + swz(lrow, lc), Bbase + st * 32);
        }
        cp_commit();
    }
    for (int kt = 0; kt < NIT; kt++) {
        cp_wait<4>();
        __syncthreads();
        int nx = kt + 5;
        if (nx < NIT) {
            uint32_t ab = smb + (nx % 6) * 8192;
            cp16(ab + swz(lrow, lc), Abase + (size_t)nx * 32);
            cp16(ab + 4096 + swz(lrow, lc), Bbase + (size_t)nx * 32);
        }
        cp_commit();
        uint32_t ab = smb + (kt % 6) * 8192;
        uint32_t bb = ab + 4096;
#pragma unroll
        for (int s = 0; s < 2; s++) {
            uint32_t af[4];
            ldm_x4(af, ab + swz(wm * 16 + a_r, s * 2 + a_c));
#pragma unroll
            for (int jj = 0; jj < 2; jj++) {
                uint32_t bf[4];
                ldm_x4(bf, bb + swz(wn * 32 + jj * 16 + b_r, s * 2 + b_c));
                mma_fp16(acc[2 * jj], af, bf[0], bf[1]);
                mma_fp16(acc[2 * jj + 1], af, bf[2], bf[3]);
            }
        }
    }
}

// ---- WIDE 64x128 tile fp16 GEMM, 5-stage (12KB/stage), single sync ------------
#define WSTG 12288
#define WSMEM (5 * WSTG)
template <int NIT>
__device__ __forceinline__ void tile_mma_w(const __half* __restrict__ Ag,
                                           const __half* __restrict__ Bg,
                                           int bm, int bn, int koff, char* spipe,
                                           float acc[8][4]) {
    uint32_t smb = smem_u32(spipe);
    int tid = threadIdx.x;
    int wid = tid >> 5, lane = tid & 31;
    int wm = wid & 3, wn = wid >> 2;
    int a_r = lane & 15, a_c = lane >> 4;
    int b_r = (lane & 7) | (((lane >> 4) & 1) << 3);
    int b_c = (lane >> 3) & 1;
#pragma unroll
    for (int q = 0; q < 8; q++)
#pragma unroll
        for (int j = 0; j < 4; j++) acc[q][j] = 0.f;

    int arow = tid >> 2, ac = tid & 3;
    const __half* Abase = Ag + (size_t)(bm + arow) * LKP + koff + ac * 8;
    const __half* B0 = Bg + (size_t)(bn + arow) * LKP + koff + ac * 8;
    const __half* B1 = Bg + (size_t)(bn + 64 + arow) * LKP + koff + ac * 8;
    uint32_t aoff = swz(arow, ac);
    uint32_t boff0 = 4096 + swz(arow, ac);
    uint32_t boff1 = 4096 + swz(64 + arow, ac);

#pragma unroll
    for (int st = 0; st < 4; st++) {
        if (st < NIT) {
            uint32_t base = smb + st * WSTG;
            cp16(base + aoff, Abase + st * 32);
            cp16(base + boff0, B0 + st * 32);
            cp16(base + boff1, B1 + st * 32);
        }
        cp_commit();
    }
    for (int kt = 0; kt < NIT; kt++) {
        cp_wait<3>();
        __syncthreads();
        int nx = kt + 4;
        if (nx < NIT) {
            uint32_t base = smb + (nx % 5) * WSTG;
            cp16(base + aoff, Abase + (size_t)nx * 32);
            cp16(base + boff0, B0 + (size_t)nx * 32);
            cp16(base + boff1, B1 + (size_t)nx * 32);
        }
        cp_commit();
        uint32_t ab = smb + (kt % 5) * WSTG;
        uint32_t bb = ab + 4096;
#pragma unroll
        for (int s = 0; s < 2; s++) {
            uint32_t af[4];
            ldm_x4(af, ab + swz(wm * 16 + a_r, s * 2 + a_c));
#pragma unroll
            for (int jj = 0; jj < 4; jj++) {
                uint32_t bf[4];
                ldm_x4(bf, bb + swz(wn * 64 + jj * 16 + b_r, s * 2 + b_c));
                mma_fp16(acc[2 * jj], af, bf[0], bf[1]);
                mma_fp16(acc[2 * jj + 1], af, bf[2], bf[3]);
            }
        }
    }
}

// ---------------- setup kernels (4 launches before loop) ------------------------
__global__ void zero_all_kernel() {
    size_t stride = (size_t)gridDim.x * blockDim.x;
    size_t id = (size_t)blockIdx.x * blockDim.x + threadIdx.x;
    uint4 z = make_uint4(0, 0, 0, 0);
    uint4* pa = (uint4*)g_Aattn;
    size_t nA = sizeof(g_Aattn) / 16;
    for (size_t i = id; i < nA; i += stride) pa[i] = z;
    uint4* pc = (uint4*)g_Acomb;
    for (size_t i = id; i < nA; i += stride) pc[i] = z;
    uint4* pi = (uint4*)g_Aih;
    size_t nI = sizeof(g_Aih) / 16;
    for (size_t i = id; i < nI; i += stride) pi[i] = z;
    uint4* ps = (uint4*)g_cst;
    size_t nS = sizeof(g_cst) / 16;
    for (size_t i = id; i < nS; i += stride) ps[i] = z;
}

__global__ void setup_enc_kernel(const float* __restrict__ enc) {
    size_t stride = (size_t)gridDim.x * blockDim.x;
    size_t total = (size_t)BB * CC * FF;
    for (size_t i = (size_t)blockIdx.x * blockDim.x + threadIdx.x; i < total; i += stride)
        g_enc2[i] = __float2half(enc[i]);
}

__global__ void setup_x2_kernel(const float* __restrict__ wv) {
    int idx = blockIdx.x * blockDim.x + threadIdx.x;
    const int total = TT * BB * WVV;
    if (idx >= total) return;
    int t = idx / (BB * WVV);
    int r = idx % (BB * WVV);
    int b = r / WVV, w = r % WVV;
    float v = (t == 0) ? 0.f : wv[(size_t)b * TT * WVV + (size_t)(t - 1) * WVV + w];
    __half hi, lo;
    split_fp16(v, hi, lo);
    size_t base = ((size_t)t * BB + b) * LKP;
    g_Aattn[base + w] = hi;
    g_Aattn[base + KSEC + w] = lo;
    g_Acomb[base + w] = hi;
    g_Acomb[base + KSEC + w] = lo;
}

#define NW0 (768 * KSEC)
#define NW1 (320 * KSEC)
#define NW2 (2048 * KSEC)
#define NW3 (NPAD * HH)
__global__ void setup_weights_kernel(const float* __restrict__ attn_W,
                                     const float* __restrict__ gate_W,
                                     const float* __restrict__ comb_W,
                                     const float* __restrict__ Wih,
                                     const float* __restrict__ Whh,
                                     const float* __restrict__ bih,
                                     const float* __restrict__ bhh,
                                     const float* __restrict__ vw) {
    long idx = (long)blockIdx.x * blockDim.x + threadIdx.x;
    if (idx < 2048) g_bl[idx] = bih[idx] + bhh[idx];
    __half hi, lo;
    if (idx < NW0) {
        int n = idx / KSEC, k = idx % KSEC;
        float v = 0.f;
        if (k < XK) {
            if (n < FF) v = attn_W[(size_t)n * XK + k];
            else if (n < NAG && k >= WVV) v = gate_W[(size_t)(n - FF) * HH + (k - WVV)];
        }
        split_fp16(v, hi, lo);
        size_t base = (size_t)n * LKP;
        g_Wag2[base + k] = hi;
        g_Wag2[base + KSEC + k] = lo;
        return;
    }
    idx -= NW0;
    if (idx < NW1) {
        int n = idx / KSEC, k = idx % KSEC;
        float v = (n < WVV && k < XK) ? comb_W[(size_t)n * XK + k] : 0.f;
        split_fp16(v, hi, lo);
        size_t base = (size_t)n * LKP;
        g_Wcomb2[base + k] = hi;
        g_Wcomb2[base + KSEC + k] = lo;
        return;
    }
    idx -= NW1;
    if (idx < NW2) {
        int n = idx / KSEC, k = idx % KSEC;
        float v = 0.f;
        if (k < XK) v = (k < WVV) ? Wih[(size_t)n * WVV + k] : Whh[(size_t)n * HH + (k - WVV)];
        split_fp16(v, hi, lo);
        size_t base = (size_t)n * LKP;
        g_Wl2[base + k] = hi;
        g_Wl2[base + KSEC + k] = lo;
        return;
    }
    idx -= NW2;
    if (idx < NW3) {
        int n = idx / HH, k = idx % HH;
        float v = (n < VV) ? vw[(size_t)n * HH + k] : 0.f;
        g_wp2[(size_t)n * KP2 + k] = __float2half(v);
    }
}

// ---------------- loop kernels (5 per step) --------------------------------------
// P1: attn+gate logits, WIDE tiles, split-2. grid = 4m x 6n x 2z = 48
__global__ void __launch_bounds__(256) k_p1(const __half* __restrict__ A) {
    extern __shared__ __align__(16) char s_dyn[];
    float acc[8][4];
    int job = blockIdx.x;
    int z = job & 1, tile = job >> 1;
    int bm = (tile / 6) * 64, bn = (tile % 6) * 128;
    tile_mma_w<NSEC>(A, g_Wag2, bm, bn, z * KSEC, s_dyn, acc);
    int tid = threadIdx.x, wid = tid >> 5, lane = tid & 31;
    float* dst = g_ag_s + (size_t)z * BB * 768;
    int r0 = bm + (wid & 3) * 16 + (lane >> 2);
    int c0 = bn + (wid >> 2) * 64 + 2 * (lane & 3);
#pragma unroll
    for (int q = 0; q < 8; q++)
#pragma unroll
        for (int h = 0; h < 2; h++) {
            dst[(r0 + 8 * h) * 768 + c0 + q * 8] = acc[q][2 * h];
            dst[(r0 + 8 * h) * 768 + c0 + q * 8 + 1] = acc[q][2 * h + 1];
        }
}

// P2: softmax + gated ctx (sums 2 slices, fp16 encoding). grid = BB
__global__ void __launch_bounds__(256)
k_p2(const float* __restrict__ attn_b, const float* __restrict__ gate_b,
     __half* __restrict__ Acomb_t) {
    __shared__ float s_red[256];
    __shared__ __align__(16) float s_aw[196];
    int b = blockIdx.x;
    int tid = threadIdx.x;
    int wid = tid >> 5, lane = tid & 31;
    const float* p0 = g_ag_s + (size_t)b * 768;
    const float* p1 = p0 + (size_t)BB * 768;
    float v = -3.0e38f;
    if (tid < FF) v = attn_b[tid] + p0[tid] + p1[tid];
    s_red[tid] = v;
    __syncthreads();
    for (int s = 128; s > 0; s >>= 1) {
        if (tid < s) s_red[tid] = fmaxf(s_red[tid], s_red[tid + s]);
        __syncthreads();
    }
    float mx = s_red[0];
    __syncthreads();
    float e = (tid < FF) ? expf(v - mx) : 0.f;
    s_red[tid] = e;
    __syncthreads();
    for (int s = 128; s > 0; s >>= 1) {
        if (tid < s) s_red[tid] += s_red[tid + s];
        __syncthreads();
    }
    float inv = 1.f / s_red[0];
    __syncthreads();
    if (tid < FF) s_aw[tid] = e * inv;
    __syncthreads();
    const __half2* encb = (const __half2*)(g_enc2 + (size_t)b * CC * FF);
    size_t cbase = (size_t)b * LKP;
    for (int grp = 0; grp < 8; grp++) {
#pragma unroll
        for (int ci = 0; ci < 8; ci++) {
            int c = wid * 64 + grp * 8 + ci;
            const __half2* row = encb + (size_t)c * 98;  // 196 halves = 98 half2
            float sum = 0.f;
#pragma unroll
            for (int it = 0; it < 4; it++) {
                int f = lane + it * 32;
                if (f < 98) {
                    float2 vf = __half22float2(row[f]);
                    sum += vf.x * s_aw[2 * f] + vf.y * s_aw[2 * f + 1];
                }
            }
#pragma unroll
            for (int o = 16; o > 0; o >>= 1) sum += __shfl_xor_sync(0xffffffffu, sum, o);
            if (lane == 0) {
                float gz = gate_b[c] + p0[FF + c] + p1[FF + c];
                float gamma = 1.f / (1.f + expf(-gz));
                float val = gamma * sum;
                __half hi, lo;
                split_fp16(val, hi, lo);
                Acomb_t[cbase + WVV + c] = hi;
                Acomb_t[cbase + KSEC + WVV + c] = lo;
            }
        }
    }
}

// P3: comb gemm FULL-K (52 iters) + fused bias/relu/split epilogue. grid = 20
__global__ void __launch_bounds__(256)
k_p3(const __half* __restrict__ A, const float* __restrict__ comb_b) {
    __shared__ __align__(16) char s_pipe[6 * 8192];
    float acc[4][4];
    int job = blockIdx.x;
    int bm = (job / 5) * 64, bn = (job % 5) * 64;
    tile_mma<2 * NSEC>(A, g_Wcomb2, bm, bn, 0, s_pipe, acc);
    int tid = threadIdx.x, wid = tid >> 5, lane = tid & 31;
    int r0 = bm + (wid & 3) * 16 + (lane >> 2);
    int c0 = bn + (wid >> 2) * 32 + 2 * (lane & 3);
#pragma unroll
    for (int q = 0; q < 4; q++)
#pragma unroll
        for (int h = 0; h < 2; h++) {
            int gm = r0 + 8 * h;
            size_t abase = (size_t)gm * LKP;
#pragma unroll
            for (int u = 0; u < 2; u++) {
                int n = c0 + q * 8 + u;
                if (n < WVV) {
                    float val = fmaxf(acc[q][2 * h + u] + comb_b[n], 0.f);
                    __half hi, lo;
                    split_fp16(val, hi, lo);
                    g_Aih[abase + n] = hi;
                    g_Aih[abase + KSEC + n] = lo;
                }
            }
        }
}

// P4: lstm gates gemm, WIDE tiles, split-2. grid = 4m x 16n x 2z = 128
__global__ void __launch_bounds__(256) k_p4() {
    extern __shared__ __align__(16) char s_dyn[];
    float acc[8][4];
    int job = blockIdx.x;
    int z = job & 1, tile = job >> 1;
    int bm = (tile / 16) * 64, bn = (tile % 16) * 128;
    tile_mma_w<NSEC>(g_Aih, g_Wl2, bm, bn, z * KSEC, s_dyn, acc);
    int tid = threadIdx.x, wid = tid >> 5, lane = tid & 31;
    float* dst = g_gate_s + (size_t)z * BB * 2048;
    int r0 = bm + (wid & 3) * 16 + (lane >> 2);
    int c0 = bn + (wid >> 2) * 64 + 2 * (lane & 3);
#pragma unroll
    for (int q = 0; q < 8; q++)
#pragma unroll
        for (int h = 0; h < 2; h++) {
            dst[(r0 + 8 * h) * 2048 + c0 + q * 8] = acc[q][2 * h];
            dst[(r0 + 8 * h) * 2048 + c0 + q * 8 + 1] = acc[q][2 * h + 1];
        }
}

// P5: LSTM cell elementwise, sums 2 gate slices. grid = 512
__global__ void __launch_bounds__(256)
k_p5(int t, __half* __restrict__ Aattn_next) {
    int idx = blockIdx.x * 256 + threadIdx.x;
    int b = idx >> 9, j = idx & 511;
    size_t gb = (size_t)b * 2048;
    const float* g0 = g_gate_s + gb;
    const float* g1 = g0 + (size_t)BB * 2048;
    float i_ = g_bl[j] + g0[j] + g1[j];
    float f_ = g_bl[512 + j] + g0[512 + j] + g1[512 + j];
    float g_ = g_bl[1024 + j] + g0[1024 + j] + g1[1024 + j];
    float o_ = g_bl[1536 + j] + g0[1536 + j] + g1[1536 + j];
    float si = 1.f / (1.f + expf(-i_));
    float sf = 1.f / (1.f + expf(-f_));
    float so = 1.f / (1.f + expf(-o_));
    float cn = sf * g_cst[idx] + si * tanhf(g_);
    float hn = so * tanhf(cn);
    g_cst[idx] = cn;
    __half hi, lo;
    split_fp16(hn, hi, lo);
    size_t ib = (size_t)b * LKP + WVV + j;
    g_Aih[ib] = hi;
    g_Aih[ib + KSEC] = lo;
    if (Aattn_next) {
        size_t ab = (size_t)b * LKP + WVV + j;
        Aattn_next[ab] = hi;
        Aattn_next[ab + KSEC] = lo;
    }
    g_ap2[((size_t)t * BB + b) * KP2 + j] = hi;
}

// ===================== vocab GEMM (fp16, one launch at end) =====================
#define VBM 128
#define VBN 256
#define NKT2 (KP2 / 32)    // 16
#define STAGE_BYTES 24576
#define ASZ 8192
#define NSTAGE 3
#define VSMEM (NSTAGE * STAGE_BYTES)

__device__ __forceinline__ void issue_tile(const __half* __restrict__ Ag,
                                           const __half* __restrict__ Bg,
                                           uint32_t smb, int stage, int bm, int bn, int kt) {
    int tid = threadIdx.x;
    uint32_t abase = smb + stage * STAGE_BYTES;
    uint32_t bbase = abase + ASZ;
#pragma unroll
    for (int l = 0; l < 2; l++) {
        int idx = tid + 256 * l;
        int row = idx >> 2, c = idx & 3;
        cp16(abase + swz(row, c), Ag + (size_t)(bm + row) * KP2 + kt * 32 + c * 8);
    }
#pragma unroll
    for (int l = 0; l < 4; l++) {
        int idx = tid + 256 * l;
        int row = idx >> 2, c = idx & 3;
        cp16(bbase + swz(row, c), Bg + (size_t)(bn + row) * KP2 + kt * 32 + c * 8);
    }
    cp_commit();
}

__global__ void __launch_bounds__(256, 1)
gemm_vocab_mma(const __half* __restrict__ Ag, const __half* __restrict__ Bg,
               const float* __restrict__ bias, float* __restrict__ out) {
    extern __shared__ char sm[];
    uint32_t smb = smem_u32(sm);
    int tid = threadIdx.x;
    int wid = tid >> 5, lane = tid & 31;
    int wm = wid & 1, wn = wid >> 1;
    int bm = blockIdx.y * VBM, bn = blockIdx.x * VBN;

    int a_r = lane & 15;
    int a_c = lane >> 4;
    int b_r = (lane & 7) | (((lane >> 4) & 1) << 3);
    int b_c = (lane >> 3) & 1;

    float acc[4][8][4];
#pragma unroll
    for (int i = 0; i < 4; i++)
#pragma unroll
        for (int j = 0; j < 8; j++)
#pragma unroll
            for (int q = 0; q < 4; q++) acc[i][j][q] = 0.f;

    issue_tile(Ag, Bg, smb, 0, bm, bn, 0);
    issue_tile(Ag, Bg, smb, 1, bm, bn, 1);

    for (int kt = 0; kt < NKT2; kt++) {
        cp_wait<1>();
        __syncthreads();
        if (kt + 2 < NKT2) issue_tile(Ag, Bg, smb, (kt + 2) % NSTAGE, bm, bn, kt + 2);
        uint32_t abase = smb + (kt % NSTAGE) * STAGE_BYTES;
        uint32_t bbase = abase + ASZ;
#pragma unroll
        for (int s = 0; s < 2; s++) {
            uint32_t af[4][4], bf[4][4];
#pragma unroll
            for (int i = 0; i < 4; i++) {
                int row = wm * 64 + i * 16 + a_r;
                ldm_x4(af[i], abase + swz(row, s * 2 + a_c));
            }
#pragma unroll
            for (int jj = 0; jj < 4; jj++) {
                int row = wn * 64 + jj * 16 + b_r;
                ldm_x4(bf[jj], bbase + swz(row, s * 2 + b_c));
            }
#pragma unroll
            for (int i = 0; i < 4; i++)
#pragma unroll
                for (int jj = 0; jj < 4; jj++) {
                    mma_fp16(acc[i][2 * jj], af[i], bf[jj][0], bf[jj][1]);
                    mma_fp16(acc[i][2 * jj + 1], af[i], bf[jj][2], bf[jj][3]);
                }
        }
    }

#pragma unroll
    for (int i = 0; i < 4; i++) {
#pragma unroll
        for (int j = 0; j < 8; j++) {
            int gm0 = bm + wm * 64 + i * 16 + (lane >> 2);
            int gn = bn + wn * 64 + j * 8 + 2 * (lane & 3);
#pragma unroll
            for (int h = 0; h < 2; h++) {
                int gm = gm0 + h * 8;
                int t = gm >> 8, b = gm & 255;
                float* row = out + ((size_t)b * TT + t) * VV;
                float c0 = acc[i][j][2 * h], c1 = acc[i][j][2 * h + 1];
                if (gn < VV) row[gn] = c0 + bias[gn];
                if (gn + 1 < VV) row[gn + 1] = c1 + bias[gn + 1];
            }
        }
    }
}

// ---------------- host launch (single stream, zero events) ----------------------
extern "C" void kernel_launch(void* const* d_in, const int* in_sizes, int n_in,
                              void* d_out, int out_size) {
    const float* enc     = (const float*)d_in[0];
    const float* wv      = (const float*)d_in[1];
    const float* attn_W  = (const float*)d_in[2];
    const float* attn_b  = (const float*)d_in[3];
    const float* comb_W  = (const float*)d_in[4];
    const float* comb_b  = (const float*)d_in[5];
    const float* gate_W  = (const float*)d_in[6];
    const float* gate_b  = (const float*)d_in[7];
    const float* Wih     = (const float*)d_in[8];
    const float* Whh     = (const float*)d_in[9];
    const float* bih     = (const float*)d_in[10];
    const float* bhh     = (const float*)d_in[11];
    const float* vocab_W = (const float*)d_in[12];
    const float* vocab_b = (const float*)d_in[13];
    float* out = (float*)d_out;

    __half *p_Aattn, *p_Acomb, *p_ap2, *p_wp2;
    cudaGetSymbolAddress((void**)&p_Aattn, g_Aattn);
    cudaGetSymbolAddress((void**)&p_Acomb, g_Acomb);
    cudaGetSymbolAddress((void**)&p_ap2, g_ap2);
    cudaGetSymbolAddress((void**)&p_wp2, g_wp2);

    cudaFuncSetAttribute(gemm_vocab_mma, cudaFuncAttributeMaxDynamicSharedMemorySize, VSMEM);
    cudaFuncSetAttribute(k_p1, cudaFuncAttributeMaxDynamicSharedMemorySize, WSMEM);
    cudaFuncSetAttribute(k_p4, cudaFuncAttributeMaxDynamicSharedMemorySize, WSMEM);

    zero_all_kernel<<<1024, 256>>>();
    setup_enc_kernel<<<2048, 256>>>(enc);
    setup_x2_kernel<<<(TT * BB * WVV + 255) / 256, 256>>>(wv);
    {
        long total = (long)NW0 + NW1 + NW2 + NW3;
        setup_weights_kernel<<<(unsigned)((total + 255) / 256), 256>>>(
            attn_W, gate_W, comb_W, Wih, Whh, bih, bhh, vocab_W);
    }

    for (int t = 0; t < TT; t++) {
        const __half* Aat = p_Aattn + (size_t)t * BB * LKP;
        __half* Aco = p_Acomb + (size_t)t * BB * LKP;
        k_p1<<<48, 256, WSMEM>>>(Aat);
        k_p2<<<BB, 256>>>(attn_b, gate_b, Aco);
        k_p3<<<20, 256>>>(Aco, comb_b);
        k_p4<<<128, 256, WSMEM>>>();
        __half* Anext = (t + 1 < TT) ? (p_Aattn + (size_t)(t + 1) * BB * LKP) : (__half*)nullptr;
        k_p5<<<512, 256>>>(t, Anext);
    }
    gemm_vocab_mma<<<dim3(NPAD / VBN, MROWS / VBM), 256, VSMEM>>>(p_ap2, p_wp2, vocab_b, out);
}